// round 5
// baseline (speedup 1.0000x reference)
#include <cuda_runtime.h>
#include <cstdint>
#include <cstddef>

#define NPIX 16384
#define CHN 128
#define BATCH 4
#define NSLICE 64

// ---------------- scratch (device globals; no allocation allowed) -------------
__device__ float g_cat[BATCH * CHN * NPIX];           // concat(x1,x2), tf32-rounded
__device__ float g_buf1[BATCH * CHN * NPIX];          // conv1 out (leaky, tf32-rounded)
__device__ float g_feat[BATCH * CHN * NPIX];          // 1x1 out, then feat, then V
__device__ float g_gpart[NSLICE * BATCH * CHN * CHN];
__device__ float g_G[BATCH * CHN * CHN];
__device__ float g_tpart[NSLICE * BATCH * CHN * 64];
__device__ float g_t2[BATCH * CHN * 64];
__device__ uint32_t g_wr1[16 * 9 * 8 * 32 * 4];       // repacked tf32 weight fragments
__device__ uint32_t g_wr2[16 * 9 * 8 * 32 * 4];
__device__ uint32_t g_wir[16 * 8 * 32 * 4];

__device__ __forceinline__ float leakyf(float v) { return v >= 0.f ? v : 0.2f * v; }

__device__ __forceinline__ uint32_t f2tf32(float f) {
    uint32_t o;
    asm("cvt.rna.tf32.f32 %0, %1;" : "=r"(o) : "f"(f));
    return o;
}
__device__ __forceinline__ float tf32r(float f) { return __uint_as_float(f2tf32(f)); }

__device__ __forceinline__ void mma_tf32(float* acc, const uint4& a, uint32_t b0, uint32_t b1) {
    asm volatile(
        "mma.sync.aligned.m16n8k8.row.col.f32.tf32.tf32.f32 "
        "{%0,%1,%2,%3}, {%4,%5,%6,%7}, {%8,%9}, {%0,%1,%2,%3};"
        : "+f"(acc[0]), "+f"(acc[1]), "+f"(acc[2]), "+f"(acc[3])
        : "r"(a.x), "r"(a.y), "r"(a.z), "r"(a.w), "r"(b0), "r"(b1));
}

__device__ __forceinline__ uint32_t smem_u32(const void* p) {
    return (uint32_t)__cvta_generic_to_shared(p);
}
__device__ __forceinline__ void cp16(uint32_t s, const void* g) {
    asm volatile("cp.async.cg.shared.global [%0], [%1], 16;" :: "r"(s), "l"(g));
}
__device__ __forceinline__ void cp4z(uint32_t s, const void* g, int valid) {
    asm volatile("cp.async.ca.shared.global [%0], [%1], 4, %2;" :: "r"(s), "l"(g), "r"(valid));
}
#define CP_COMMIT() asm volatile("cp.async.commit_group;")
#define CP_WAIT1() asm volatile("cp.async.wait_group 1;")
#define CP_WAIT0() asm volatile("cp.async.wait_group 0;")

// ---------------- prep: concat + tf32-round ----------------------------------
__global__ void prep_cat_kernel(const float* __restrict__ x1, const float* __restrict__ x2)
{
    int i4 = blockIdx.x * 256 + threadIdx.x;
    if (i4 >= (BATCH * CHN * NPIX) / 4) return;
    size_t base = (size_t)i4 * 4;
    int b = (int)(base >> 21);
    int rem = (int)(base & ((1u << 21) - 1));
    int ic = rem >> 14;
    int n = rem & (NPIX - 1);
    const float* src = (ic < 64) ? x1 + ((size_t)(b * 64 + ic) << 14) + n
                                 : x2 + ((size_t)(b * 64 + ic - 64) << 14) + n;
    float4 v = *(const float4*)src;
    v.x = tf32r(v.x); v.y = tf32r(v.y); v.z = tf32r(v.z); v.w = tf32r(v.w);
    *(float4*)(g_cat + base) = v;
}

// ---------------- weight repack (all 3 in one launch) -------------------------
__device__ __forceinline__ void repack_w3(const float* __restrict__ w, uint32_t* __restrict__ out,
                                          int idx)
{
    int lane = idx & 31;
    int t2 = idx >> 5;
    int ocg = t2 & 7;
    int t3 = t2 >> 3;
    int tap = t3 % 9;
    int chunk = t3 / 9;
    int oc = ocg * 16 + (lane >> 2);
    int ic = chunk * 8 + (lane & 3);
    uint32_t* o = out + (size_t)idx * 4;
    o[0] = f2tf32(w[((size_t)oc * CHN + ic) * 9 + tap]);
    o[1] = f2tf32(w[((size_t)(oc + 8) * CHN + ic) * 9 + tap]);
    o[2] = f2tf32(w[((size_t)oc * CHN + ic + 4) * 9 + tap]);
    o[3] = f2tf32(w[((size_t)(oc + 8) * CHN + ic + 4) * 9 + tap]);
}

__global__ void repack_all_kernel(const float* __restrict__ w1, const float* __restrict__ w2,
                                  const float* __restrict__ wi,
                                  uint32_t* __restrict__ wr1, uint32_t* __restrict__ wr2,
                                  uint32_t* __restrict__ wir)
{
    int bx = blockIdx.x;
    if (bx < 144) {
        int idx = bx * 256 + threadIdx.x;
        if (idx < 16 * 9 * 8 * 32) repack_w3(w1, wr1, idx);
    } else if (bx < 288) {
        int idx = (bx - 144) * 256 + threadIdx.x;
        if (idx < 16 * 9 * 8 * 32) repack_w3(w2, wr2, idx);
    } else {
        int idx = (bx - 288) * 256 + threadIdx.x;
        if (idx >= 16 * 8 * 32) return;
        int lane = idx & 31;
        int ocg = (idx >> 5) & 7;
        int chunk = idx >> 8;
        int oc = ocg * 16 + (lane >> 2);
        int ic = chunk * 8 + (lane & 3);
        uint32_t* o = wir + (size_t)idx * 4;
        o[0] = f2tf32(wi[(size_t)oc * CHN + ic]);
        o[1] = f2tf32(wi[(size_t)(oc + 8) * CHN + ic]);
        o[2] = f2tf32(wi[(size_t)oc * CHN + ic + 4]);
        o[3] = f2tf32(wi[(size_t)(oc + 8) * CHN + ic + 4]);
    }
}

// ---------------- conv 3x3 via tf32 mma, cp.async double-buffered ------------
#define SW_CNT 2304
#define SIN_CNT 1920
#define CONV_SMEM 89088

template <bool FIRST>
__device__ __forceinline__ void conv_stage(int tid, int buf, int cc, int b, int r0, int c0,
                                           uint4* sW, float* sIn, const uint4* wsrc)
{
    const uint4* ws = wsrc + (size_t)cc * SW_CNT;
    uint4* wd = sW + buf * SW_CNT;
    for (int i = tid; i < SW_CNT; i += 256) cp16(smem_u32(wd + i), ws + i);

    const float* src = FIRST ? g_cat : g_buf1;
    const float* pb = src + ((size_t)b * CHN + cc * 8) * NPIX;
    float* ind = sIn + buf * SIN_CNT;
    for (int idx = tid; idx < 1440; idx += 256) {
        int r = idx / 144;
        int rem = idx - r * 144;
        int ic = rem / 18;
        int px = rem - ic * 18;
        int gr = r0 - 1 + r, gc = c0 - 1 + px;
        bool ok = ((unsigned)gr < 128u) && ((unsigned)gc < 128u);
        const float* g = pb + (size_t)ic * NPIX + (ok ? gr * 128 + gc : 0);
        cp4z(smem_u32(ind + (r * 8 + ic) * 24 + px), g, ok ? 4 : 0);
    }
}

template <bool FIRST>
__global__ __launch_bounds__(256, 2) void conv_mma_kernel(const float* __restrict__ bias)
{
    extern __shared__ char smem[];
    uint4* sW = (uint4*)smem;
    float* sIn = (float*)(smem + 73728);

    const int tid = threadIdx.x;
    const int lane = tid & 31;
    const int wid = tid >> 5;
    const int warpM = wid & 3;
    const int warpN = wid >> 2;
    const int lq = lane >> 2;
    const int lr = lane & 3;
    const int b = blockIdx.z;
    const int r0 = blockIdx.y * 8;
    const int c0 = blockIdx.x * 16;

    float acc[2][8][4];
#pragma unroll
    for (int m = 0; m < 2; m++)
#pragma unroll
        for (int j = 0; j < 8; j++)
#pragma unroll
            for (int e = 0; e < 4; e++) acc[m][j][e] = 0.f;

    const uint4* wsrc = (const uint4*)(FIRST ? g_wr1 : g_wr2);

    conv_stage<FIRST>(tid, 0, 0, b, r0, c0, sW, sIn, wsrc);
    CP_COMMIT();

    for (int cc = 0; cc < 16; cc++) {
        if (cc < 15) {
            conv_stage<FIRST>(tid, (cc + 1) & 1, cc + 1, b, r0, c0, sW, sIn, wsrc);
            CP_COMMIT();
            CP_WAIT1();
        } else {
            CP_WAIT0();
        }
        __syncthreads();

        const uint4* sWb = sW + (cc & 1) * SW_CNT;
        const float* sInb = sIn + (cc & 1) * SIN_CNT;
#pragma unroll
        for (int tap = 0; tap < 9; tap++) {
            const int dr = tap / 3, dc = tap % 3;
            uint4 af0 = sWb[(tap * 8 + warpM * 2 + 0) * 32 + lane];
            uint4 af1 = sWb[(tap * 8 + warpM * 2 + 1) * 32 + lane];
#pragma unroll
            for (int j = 0; j < 8; j++) {
                int row = warpN * 4 + (j >> 1) + dr;
                int pxb = (j & 1) * 8 + lq + dc;
                uint32_t b0 = __float_as_uint(sInb[(row * 8 + lr) * 24 + pxb]);
                uint32_t b1 = __float_as_uint(sInb[(row * 8 + lr + 4) * 24 + pxb]);
                mma_tf32(acc[0][j], af0, b0, b1);
                mma_tf32(acc[1][j], af1, b0, b1);
            }
        }
        __syncthreads();
    }

#pragma unroll
    for (int m = 0; m < 2; m++) {
        int oc = warpM * 32 + m * 16 + lq;
        float bv0 = bias[oc], bv1 = bias[oc + 8];
#pragma unroll
        for (int j = 0; j < 8; j++) {
            int irow = r0 + warpN * 4 + (j >> 1);
            int icol = c0 + (j & 1) * 8 + lr * 2;
            size_t base0 = ((size_t)(b * CHN + oc) * 128 + irow) * 128 + icol;
            size_t base1 = base0 + (size_t)8 * NPIX;
            if (FIRST) {
                float2 v0, v1;
                v0.x = tf32r(leakyf(acc[m][j][0] + bv0));
                v0.y = tf32r(leakyf(acc[m][j][1] + bv0));
                v1.x = tf32r(leakyf(acc[m][j][2] + bv1));
                v1.y = tf32r(leakyf(acc[m][j][3] + bv1));
                *(float2*)(g_buf1 + base0) = v0;
                *(float2*)(g_buf1 + base1) = v1;
            } else {
                float2 p0 = *(const float2*)(g_feat + base0);
                float2 p1 = *(const float2*)(g_feat + base1);
                p0.x += leakyf(acc[m][j][0] + bv0);
                p0.y += leakyf(acc[m][j][1] + bv0);
                p1.x += leakyf(acc[m][j][2] + bv1);
                p1.y += leakyf(acc[m][j][3] + bv1);
                *(float2*)(g_feat + base0) = p0;
                *(float2*)(g_feat + base1) = p1;
            }
        }
    }
}

// ---------------- 1x1 conv via tf32 mma: g_feat = wi @ cat + bi --------------
__global__ __launch_bounds__(256) void gemm1x1_kernel(const float* __restrict__ bi)
{
    __shared__ float sB[2][8 * 136];

    const int tid = threadIdx.x;
    const int lane = tid & 31;
    const int wid = tid >> 5;
    const int warpM = wid & 3;
    const int warpN = wid >> 2;
    const int lq = lane >> 2;
    const int lr = lane & 3;
    const int b = blockIdx.y;
    const int px0 = blockIdx.x * 128;

    float acc[2][8][4];
#pragma unroll
    for (int m = 0; m < 2; m++)
#pragma unroll
        for (int j = 0; j < 8; j++)
#pragma unroll
            for (int e = 0; e < 4; e++) acc[m][j][e] = 0.f;

    const uint4* wsrc = (const uint4*)g_wir;

    {
        int ic = tid >> 5, q = tid & 31;
        cp16(smem_u32(&sB[0][ic * 136 + q * 4]),
             g_cat + ((size_t)(b * CHN + ic)) * NPIX + px0 + q * 4);
    }
    CP_COMMIT();

    for (int cc = 0; cc < 16; cc++) {
        if (cc < 15) {
            int ic = tid >> 5, q = tid & 31;
            cp16(smem_u32(&sB[(cc + 1) & 1][ic * 136 + q * 4]),
                 g_cat + ((size_t)(b * CHN + (cc + 1) * 8 + ic)) * NPIX + px0 + q * 4);
            CP_COMMIT();
            CP_WAIT1();
        } else {
            CP_WAIT0();
        }
        __syncthreads();

        const float* sBb = sB[cc & 1];
        uint4 wf0 = wsrc[(cc * 8 + warpM * 2 + 0) * 32 + lane];
        uint4 wf1 = wsrc[(cc * 8 + warpM * 2 + 1) * 32 + lane];
#pragma unroll
        for (int j = 0; j < 8; j++) {
            int pxb = warpN * 64 + j * 8 + lq;
            uint32_t b0 = __float_as_uint(sBb[lr * 136 + pxb]);
            uint32_t b1 = __float_as_uint(sBb[(lr + 4) * 136 + pxb]);
            mma_tf32(acc[0][j], wf0, b0, b1);
            mma_tf32(acc[1][j], wf1, b0, b1);
        }
        __syncthreads();
    }

#pragma unroll
    for (int m = 0; m < 2; m++) {
        int oc = warpM * 32 + m * 16 + lq;
        float b0 = bi[oc], b1 = bi[oc + 8];
#pragma unroll
        for (int j = 0; j < 8; j++) {
            int px = px0 + warpN * 64 + j * 8 + lr * 2;
            size_t base0 = ((size_t)(b * CHN + oc)) * NPIX + px;
            size_t base1 = base0 + (size_t)8 * NPIX;
            float2 v0, v1;
            v0.x = acc[m][j][0] + b0; v0.y = acc[m][j][1] + b0;
            v1.x = acc[m][j][2] + b1; v1.y = acc[m][j][3] + b1;
            *(float2*)(g_feat + base0) = v0;
            *(float2*)(g_feat + base1) = v1;
        }
    }
}

// ---------------- L1 row sums + in-place scale --------------------------------
__global__ void rowsum_scale_kernel()
{
    int bc = blockIdx.x;
    float* p = g_feat + (size_t)bc * NPIX;
    float s = 0.f;
    for (int i = threadIdx.x * 4; i < NPIX; i += 1024) {
        float4 v = *(const float4*)(p + i);
        s += fabsf(v.x) + fabsf(v.y) + fabsf(v.z) + fabsf(v.w);
    }
    __shared__ float red[256];
    red[threadIdx.x] = s;
    __syncthreads();
    for (int st = 128; st > 0; st >>= 1) {
        if (threadIdx.x < st) red[threadIdx.x] += red[threadIdx.x + st];
        __syncthreads();
    }
    float inv = 1.0f / (1e-6f + red[0]);
    for (int i = threadIdx.x * 4; i < NPIX; i += 1024) {
        float4 v = *(const float4*)(p + i);
        v.x *= inv; v.y *= inv; v.z *= inv; v.w *= inv;
        *(float4*)(p + i) = v;
    }
}

// ---------------- G = V V^T via tf32 mma, split-K -----------------------------
// CTA: 128x128 output, K-slice 256 (16 chunks of 16). sV[c][k] stride 20.
// Warp tile 32(m) x 64(n): mfrag 2, nfrag 8.
__global__ __launch_bounds__(256, 2) void gemmG_mma_kernel()
{
    __shared__ float sV[2][128 * 20];
    const int tid = threadIdx.x;
    const int lane = tid & 31;
    const int wid = tid >> 5;
    const int warpM = wid & 3;
    const int warpN = wid >> 2;
    const int lq = lane >> 2;
    const int lr = lane & 3;
    const int slice = blockIdx.x, b = blockIdx.y;
    const float* base = g_feat + (size_t)b * CHN * NPIX;
    const int k0g = slice * 256;

    float acc[2][8][4];
#pragma unroll
    for (int mi = 0; mi < 2; mi++)
#pragma unroll
        for (int nj = 0; nj < 8; nj++)
#pragma unroll
            for (int e = 0; e < 4; e++) acc[mi][nj][e] = 0.f;

    // stage chunk 0: 128 c x 16 k = 512 float4
    {
        int c = tid >> 1, q = tid & 1;
        cp16(smem_u32(&sV[0][c * 20 + q * 8]), base + (size_t)c * NPIX + k0g + q * 8);
        cp16(smem_u32(&sV[0][c * 20 + q * 8 + 4]), base + (size_t)c * NPIX + k0g + q * 8 + 4);
    }
    CP_COMMIT();

    for (int kc = 0; kc < 16; kc++) {
        if (kc < 15) {
            int c = tid >> 1, q = tid & 1;
            int kk = k0g + (kc + 1) * 16;
            cp16(smem_u32(&sV[(kc + 1) & 1][c * 20 + q * 8]), base + (size_t)c * NPIX + kk + q * 8);
            cp16(smem_u32(&sV[(kc + 1) & 1][c * 20 + q * 8 + 4]),
                 base + (size_t)c * NPIX + kk + q * 8 + 4);
            CP_COMMIT();
            CP_WAIT1();
        } else {
            CP_WAIT0();
        }
        __syncthreads();
        const float* sv = sV[kc & 1];
#pragma unroll
        for (int ks = 0; ks < 2; ks++) {
            int k = ks * 8;
            uint4 af[2];
#pragma unroll
            for (int mi = 0; mi < 2; mi++) {
                int m0 = warpM * 32 + mi * 16;
                af[mi].x = __float_as_uint(sv[(m0 + lq) * 20 + k + lr]);
                af[mi].y = __float_as_uint(sv[(m0 + lq + 8) * 20 + k + lr]);
                af[mi].z = __float_as_uint(sv[(m0 + lq) * 20 + k + lr + 4]);
                af[mi].w = __float_as_uint(sv[(m0 + lq + 8) * 20 + k + lr + 4]);
            }
#pragma unroll
            for (int nj = 0; nj < 8; nj++) {
                int n0 = warpN * 64 + nj * 8;
                uint32_t b0 = __float_as_uint(sv[(n0 + lq) * 20 + k + lr]);
                uint32_t b1 = __float_as_uint(sv[(n0 + lq) * 20 + k + lr + 4]);
                mma_tf32(acc[0][nj], af[0], b0, b1);
                mma_tf32(acc[1][nj], af[1], b0, b1);
            }
        }
        __syncthreads();
    }

    float* outp = g_gpart + ((size_t)slice * BATCH + b) * CHN * CHN;
#pragma unroll
    for (int mi = 0; mi < 2; mi++) {
        int m0 = warpM * 32 + mi * 16 + lq;
#pragma unroll
        for (int nj = 0; nj < 8; nj++) {
            int n = warpN * 64 + nj * 8 + lr * 2;
            *(float2*)(outp + m0 * 128 + n) = make_float2(acc[mi][nj][0], acc[mi][nj][1]);
            *(float2*)(outp + (m0 + 8) * 128 + n) = make_float2(acc[mi][nj][2], acc[mi][nj][3]);
        }
    }
}

__global__ void reduceG_kernel()
{
    int o = blockIdx.x * 256 + threadIdx.x;
    float s = 0.f;
    for (int sl = 0; sl < NSLICE; sl++)
        s += g_gpart[(size_t)sl * (BATCH * CHN * CHN) + o];
    g_G[o] = s;
}

// ---------------- t = V @ x1^T via tf32 mma, split-K --------------------------
// CTA: 128(c) x 64(m) output, K-slice 256. Warp tile 32x32: mfrag 2, nfrag 4.
__global__ __launch_bounds__(256, 2) void gemmT_mma_kernel()
{
    __shared__ float sV[2][128 * 20];
    __shared__ float sX[2][64 * 20];
    const int tid = threadIdx.x;
    const int lane = tid & 31;
    const int wid = tid >> 5;
    const int warpM = wid & 3;
    const int warpN = wid >> 2;
    const int lq = lane >> 2;
    const int lr = lane & 3;
    const int slice = blockIdx.x, b = blockIdx.y;
    const float* vbase = g_feat + (size_t)b * CHN * NPIX;
    const float* xbase = g_cat + (size_t)b * CHN * NPIX;  // channels 0..63 = tf32(x1)
    const int k0g = slice * 256;

    float acc[2][4][4];
#pragma unroll
    for (int mi = 0; mi < 2; mi++)
#pragma unroll
        for (int nj = 0; nj < 4; nj++)
#pragma unroll
            for (int e = 0; e < 4; e++) acc[mi][nj][e] = 0.f;

    auto stage = [&](int buf, int kc) {
        int kk = k0g + kc * 16;
        int c = tid >> 1, q = tid & 1;
        cp16(smem_u32(&sV[buf][c * 20 + q * 8]), vbase + (size_t)c * NPIX + kk + q * 8);
        cp16(smem_u32(&sV[buf][c * 20 + q * 8 + 4]), vbase + (size_t)c * NPIX + kk + q * 8 + 4);
        int m = tid >> 2, q2 = tid & 3;
        cp16(smem_u32(&sX[buf][m * 20 + q2 * 4]), xbase + (size_t)m * NPIX + kk + q2 * 4);
    };

    stage(0, 0);
    CP_COMMIT();

    for (int kc = 0; kc < 16; kc++) {
        if (kc < 15) {
            stage((kc + 1) & 1, kc + 1);
            CP_COMMIT();
            CP_WAIT1();
        } else {
            CP_WAIT0();
        }
        __syncthreads();
        const float* sv = sV[kc & 1];
        const float* sx = sX[kc & 1];
#pragma unroll
        for (int ks = 0; ks < 2; ks++) {
            int k = ks * 8;
            uint4 af[2];
#pragma unroll
            for (int mi = 0; mi < 2; mi++) {
                int m0 = warpM * 32 + mi * 16;
                af[mi].x = __float_as_uint(sv[(m0 + lq) * 20 + k + lr]);
                af[mi].y = __float_as_uint(sv[(m0 + lq + 8) * 20 + k + lr]);
                af[mi].z = __float_as_uint(sv[(m0 + lq) * 20 + k + lr + 4]);
                af[mi].w = __float_as_uint(sv[(m0 + lq + 8) * 20 + k + lr + 4]);
            }
#pragma unroll
            for (int nj = 0; nj < 4; nj++) {
                int n0 = warpN * 32 + nj * 8;
                uint32_t b0 = __float_as_uint(sx[(n0 + lq) * 20 + k + lr]);
                uint32_t b1 = __float_as_uint(sx[(n0 + lq) * 20 + k + lr + 4]);
                mma_tf32(acc[0][nj], af[0], b0, b1);
                mma_tf32(acc[1][nj], af[1], b0, b1);
            }
        }
        __syncthreads();
    }

    float* outp = g_tpart + ((size_t)slice * BATCH + b) * CHN * 64;
#pragma unroll
    for (int mi = 0; mi < 2; mi++) {
        int m0 = warpM * 32 + mi * 16 + lq;
#pragma unroll
        for (int nj = 0; nj < 4; nj++) {
            int n = warpN * 32 + nj * 8 + lr * 2;
            *(float2*)(outp + m0 * 64 + n) = make_float2(acc[mi][nj][0], acc[mi][nj][1]);
            *(float2*)(outp + (m0 + 8) * 64 + n) = make_float2(acc[mi][nj][2], acc[mi][nj][3]);
        }
    }
}

// ---------------- solve: [G | t] -> G^{-1} t, in shared memory ---------------
__global__ __launch_bounds__(768) void solve_kernel()
{
    extern __shared__ float sA[];  // [128][192]
    __shared__ float fcol[128];
    __shared__ float prow[192];
    const int b = blockIdx.x, tid = threadIdx.x;

    for (int i = tid; i < 128 * 128; i += 768) {
        int r = i >> 7, c = i & 127;
        sA[r * 192 + c] = g_G[(size_t)b * CHN * CHN + i];
    }
    for (int e = tid; e < 128 * 64; e += 768) {
        float s = 0.f;
        for (int sl = 0; sl < NSLICE; sl++)
            s += g_tpart[((size_t)sl * BATCH + b) * CHN * 64 + e];
        sA[(e >> 6) * 192 + 128 + (e & 63)] = s;
    }
    __syncthreads();

    const int j = tid % 192, g = tid / 192;
    for (int p = 0; p < 128; p++) {
        if (g == 0) {
            float piv = sA[p * 192 + p];
            prow[j] = sA[p * 192 + j] * (1.0f / piv);
        } else if (g == 1 && j < 128) {
            fcol[j] = (j == p) ? 0.f : sA[j * 192 + p];
        }
        __syncthreads();
        float pr = prow[j];
        const int i0 = g * 32;
#pragma unroll 4
        for (int i = i0; i < i0 + 32; i++) {
            float v = sA[i * 192 + j] - fcol[i] * pr;
            if (i == p) v = pr;
            sA[i * 192 + j] = v;
        }
        __syncthreads();
    }

    for (int e = tid; e < 128 * 64; e += 768)
        g_t2[(size_t)b * CHN * 64 + e] = sA[(e >> 6) * 192 + 128 + (e & 63)];
}

// ---------------- proj via tf32 mma: out[m][n] = sum_c t2[c][m] V[c][n] ------
// CTA: 64(m) x 256(n), K=128 (16 chunks of 8 c). 8 warps = 8 n-slices of 32.
// smem: st2[128][72] + sVc[2][8][264] (dynamic, 53760 B)
#define PROJ_SMEM (128 * 72 * 4 + 2 * 8 * 264 * 4)
__global__ __launch_bounds__(256, 2) void proj_mma_kernel(float* __restrict__ out)
{
    extern __shared__ float psm[];
    float* st2 = psm;                 // [128][72]
    float* sVc = psm + 128 * 72;      // [2][8][264]

    const int tid = threadIdx.x;
    const int lane = tid & 31;
    const int wid = tid >> 5;
    const int lq = lane >> 2;
    const int lr = lane & 3;
    const int b = blockIdx.y;
    const int n0cta = blockIdx.x * 256;
    const float* Vb = g_feat + (size_t)b * CHN * NPIX;

    // stage t2 (cp.async group 0 stays pending alongside chunk groups; waited via WAIT)
    {
        int e4 = tid;  // 128*64/4 = 2048 float4 -> 8 per thread
        for (int i = 0; i < 8; i++, e4 += 256) {
            int c = e4 >> 4, mq = e4 & 15;
            cp16(smem_u32(st2 + c * 72 + mq * 4), g_t2 + (size_t)b * CHN * 64 + c * 64 + mq * 4);
        }
    }
    auto stageV = [&](int buf, int cc) {
        int r = tid >> 6, q = tid & 63;  // 2 rows per pass
        cp16(smem_u32(sVc + buf * 8 * 264 + r * 264 + q * 4),
             Vb + (size_t)(cc * 8 + r) * NPIX + n0cta + q * 4);
        cp16(smem_u32(sVc + buf * 8 * 264 + (r + 4) * 264 + q * 4),
             Vb + (size_t)(cc * 8 + r + 4) * NPIX + n0cta + q * 4);
    };
    stageV(0, 0);
    CP_COMMIT();

    float acc[4][4][4];
#pragma unroll
    for (int mi = 0; mi < 4; mi++)
#pragma unroll
        for (int nj = 0; nj < 4; nj++)
#pragma unroll
            for (int e = 0; e < 4; e++) acc[mi][nj][e] = 0.f;

    for (int cc = 0; cc < 16; cc++) {
        if (cc < 15) {
            stageV((cc + 1) & 1, cc + 1);
            CP_COMMIT();
            CP_WAIT1();
        } else {
            CP_WAIT0();
        }
        __syncthreads();
        const float* sv = sVc + (cc & 1) * 8 * 264;
        uint4 af[4];
#pragma unroll
        for (int mi = 0; mi < 4; mi++) {
            int m0 = mi * 16;
            int c0 = cc * 8;
            af[mi].x = __float_as_uint(st2[(c0 + lr) * 72 + m0 + lq]);
            af[mi].y = __float_as_uint(st2[(c0 + lr) * 72 + m0 + lq + 8]);
            af[mi].z = __float_as_uint(st2[(c0 + lr + 4) * 72 + m0 + lq]);
            af[mi].w = __float_as_uint(st2[(c0 + lr + 4) * 72 + m0 + lq + 8]);
        }
#pragma unroll
        for (int nj = 0; nj < 4; nj++) {
            int n0 = wid * 32 + nj * 8;
            uint32_t b0 = __float_as_uint(sv[lr * 264 + n0 + lq]);
            uint32_t b1 = __float_as_uint(sv[(lr + 4) * 264 + n0 + lq]);
#pragma unroll
            for (int mi = 0; mi < 4; mi++) mma_tf32(acc[mi][nj], af[mi], b0, b1);
        }
        __syncthreads();
    }

#pragma unroll
    for (int mi = 0; mi < 4; mi++) {
        int m0 = mi * 16 + lq;
#pragma unroll
        for (int nj = 0; nj < 4; nj++) {
            int n = n0cta + wid * 32 + nj * 8 + lr * 2;
            *(float2*)(out + ((size_t)(b * 64 + m0)) * NPIX + n) =
                make_float2(acc[mi][nj][0], acc[mi][nj][1]);
            *(float2*)(out + ((size_t)(b * 64 + m0 + 8)) * NPIX + n) =
                make_float2(acc[mi][nj][2], acc[mi][nj][3]);
        }
    }
}

// ---------------- launch -----------------------------------------------------
extern "C" void kernel_launch(void* const* d_in, const int* in_sizes, int n_in,
                              void* d_out, int out_size)
{
    const float* x1 = (const float*)d_in[0];
    const float* x2 = (const float*)d_in[1];
    const float* w1 = (const float*)d_in[2];
    const float* b1 = (const float*)d_in[3];
    const float* w2 = (const float*)d_in[4];
    const float* b2 = (const float*)d_in[5];
    const float* wi = (const float*)d_in[6];
    const float* bi = (const float*)d_in[7];
    float* out = (float*)d_out;

    static bool attr_done = false;
    if (!attr_done) {
        cudaFuncSetAttribute(solve_kernel, cudaFuncAttributeMaxDynamicSharedMemorySize,
                             128 * 192 * sizeof(float));
        cudaFuncSetAttribute(conv_mma_kernel<true>,
                             cudaFuncAttributeMaxDynamicSharedMemorySize, CONV_SMEM);
        cudaFuncSetAttribute(conv_mma_kernel<false>,
                             cudaFuncAttributeMaxDynamicSharedMemorySize, CONV_SMEM);
        cudaFuncSetAttribute(proj_mma_kernel,
                             cudaFuncAttributeMaxDynamicSharedMemorySize, PROJ_SMEM);
        attr_done = true;
    }

    uint32_t* wr1;  cudaGetSymbolAddress((void**)&wr1, g_wr1);
    uint32_t* wr2;  cudaGetSymbolAddress((void**)&wr2, g_wr2);
    uint32_t* wir;  cudaGetSymbolAddress((void**)&wir, g_wir);

    prep_cat_kernel<<<8192, 256>>>(x1, x2);
    repack_all_kernel<<<304, 256>>>(w1, w2, wi, wr1, wr2, wir);

    dim3 cgrid(8, 16, 4);
    conv_mma_kernel<true><<<cgrid, 256, CONV_SMEM>>>(b1);
    gemm1x1_kernel<<<dim3(128, 4), 256>>>(bi);
    conv_mma_kernel<false><<<cgrid, 256, CONV_SMEM>>>(b2);

    rowsum_scale_kernel<<<512, 256>>>();
    gemmG_mma_kernel<<<dim3(NSLICE, BATCH), 256>>>();
    reduceG_kernel<<<256, 256>>>();
    gemmT_mma_kernel<<<dim3(NSLICE, BATCH), 256>>>();
    solve_kernel<<<BATCH, 768, 128 * 192 * sizeof(float)>>>();
    proj_mma_kernel<<<dim3(64, BATCH), 256, PROJ_SMEM>>>(out);
}

// round 7
// speedup vs baseline: 1.1245x; 1.1245x over previous
#include <cuda_runtime.h>
#include <cuda_fp16.h>
#include <cstdint>
#include <cstddef>

#define NPIX 16384
#define CHN 128
#define BATCH 4
#define NSLICE 64

// ---------------- scratch (device globals; no allocation allowed) -------------
__device__ float g_cat[BATCH * CHN * NPIX];           // concat(x1,x2), tf32-rounded
__device__ float g_buf1[BATCH * CHN * NPIX];          // conv1 out (leaky, fp32)
__device__ float g_feat[BATCH * CHN * NPIX];          // 1x1 out, then feat, then V
__device__ float g_gpart[NSLICE * BATCH * CHN * CHN];
__device__ float g_G[BATCH * CHN * CHN];
__device__ float g_tpart[NSLICE * BATCH * CHN * 64];
__device__ float g_t2[BATCH * CHN * 64];
// fp16 conv weight fragments: [chunk8][tap9][mfrag8][lane32] uint4
__device__ uint32_t g_wh1[8 * 9 * 8 * 32 * 4];
__device__ uint32_t g_wh2[8 * 9 * 8 * 32 * 4];
__device__ uint32_t g_wir[16 * 8 * 32 * 4];           // 1x1 tf32 fragments

__device__ __forceinline__ float leakyf(float v) { return v >= 0.f ? v : 0.2f * v; }

__device__ __forceinline__ uint32_t f2tf32(float f) {
    uint32_t o;
    asm("cvt.rna.tf32.f32 %0, %1;" : "=r"(o) : "f"(f));
    return o;
}
__device__ __forceinline__ float tf32r(float f) { return __uint_as_float(f2tf32(f)); }

__device__ __forceinline__ void mma_tf32(float* acc, const uint4& a, uint32_t b0, uint32_t b1) {
    asm volatile(
        "mma.sync.aligned.m16n8k8.row.col.f32.tf32.tf32.f32 "
        "{%0,%1,%2,%3}, {%4,%5,%6,%7}, {%8,%9}, {%0,%1,%2,%3};"
        : "+f"(acc[0]), "+f"(acc[1]), "+f"(acc[2]), "+f"(acc[3])
        : "r"(a.x), "r"(a.y), "r"(a.z), "r"(a.w), "r"(b0), "r"(b1));
}
__device__ __forceinline__ void mma_f16(float* acc, const uint4& a, uint32_t b0, uint32_t b1) {
    asm volatile(
        "mma.sync.aligned.m16n8k16.row.col.f32.f16.f16.f32 "
        "{%0,%1,%2,%3}, {%4,%5,%6,%7}, {%8,%9}, {%0,%1,%2,%3};"
        : "+f"(acc[0]), "+f"(acc[1]), "+f"(acc[2]), "+f"(acc[3])
        : "r"(a.x), "r"(a.y), "r"(a.z), "r"(a.w), "r"(b0), "r"(b1));
}

__device__ __forceinline__ uint32_t smem_u32(const void* p) {
    return (uint32_t)__cvta_generic_to_shared(p);
}
__device__ __forceinline__ void cp16(uint32_t s, const void* g) {
    asm volatile("cp.async.cg.shared.global [%0], [%1], 16;" :: "r"(s), "l"(g));
}
#define CP_COMMIT() asm volatile("cp.async.commit_group;")
#define CP_WAIT1() asm volatile("cp.async.wait_group 1;")
#define CP_WAIT0() asm volatile("cp.async.wait_group 0;")

__device__ __forceinline__ uint32_t pack_h2(float lo, float hi) {
    __half2 h = __floats2half2_rn(lo, hi);
    return *(uint32_t*)&h;
}
// permuted ic position inside 16-ic group (so one LDS.64 yields {b0,b1})
__device__ __forceinline__ int icpos(int k) {
    return (k < 8) ? ((k >> 1) * 4 + (k & 1)) : (((k - 8) >> 1) * 4 + 2 + (k & 1));
}

// ---------------- prep: concat + tf32-round ----------------------------------
__global__ void prep_cat_kernel(const float* __restrict__ x1, const float* __restrict__ x2)
{
    int i4 = blockIdx.x * 256 + threadIdx.x;
    if (i4 >= (BATCH * CHN * NPIX) / 4) return;
    size_t base = (size_t)i4 * 4;
    int b = (int)(base >> 21);
    int rem = (int)(base & ((1u << 21) - 1));
    int ic = rem >> 14;
    int n = rem & (NPIX - 1);
    const float* src = (ic < 64) ? x1 + ((size_t)(b * 64 + ic) << 14) + n
                                 : x2 + ((size_t)(b * 64 + ic - 64) << 14) + n;
    float4 v = *(const float4*)src;
    v.x = tf32r(v.x); v.y = tf32r(v.y); v.z = tf32r(v.z); v.w = tf32r(v.w);
    *(float4*)(g_cat + base) = v;
}

// ---------------- weight repack ----------------------------------------------
// fp16 conv frags: idx = ((chunk*9+tap)*8+mf)*32+lane
__device__ __forceinline__ void repack_wh(const float* __restrict__ w, uint4* __restrict__ out,
                                          int idx)
{
    int lane = idx & 31;
    int t = idx >> 5;
    int mf = t & 7;
    int t2 = t >> 3;
    int tap = t2 % 9;
    int chunk = t2 / 9;
    int lq = lane >> 2, lr = lane & 3;
    int oc0 = mf * 16 + lq, oc1 = oc0 + 8;
    int kb = chunk * 16;
    uint4 o;
    o.x = pack_h2(w[((size_t)oc0 * CHN + kb + 2 * lr) * 9 + tap],
                  w[((size_t)oc0 * CHN + kb + 2 * lr + 1) * 9 + tap]);
    o.y = pack_h2(w[((size_t)oc1 * CHN + kb + 2 * lr) * 9 + tap],
                  w[((size_t)oc1 * CHN + kb + 2 * lr + 1) * 9 + tap]);
    o.z = pack_h2(w[((size_t)oc0 * CHN + kb + 8 + 2 * lr) * 9 + tap],
                  w[((size_t)oc0 * CHN + kb + 9 + 2 * lr) * 9 + tap]);
    o.w = pack_h2(w[((size_t)oc1 * CHN + kb + 8 + 2 * lr) * 9 + tap],
                  w[((size_t)oc1 * CHN + kb + 9 + 2 * lr) * 9 + tap]);
    out[idx] = o;
}

__global__ void repack_all_kernel(const float* __restrict__ w1, const float* __restrict__ w2,
                                  const float* __restrict__ wi,
                                  uint32_t* __restrict__ wh1, uint32_t* __restrict__ wh2,
                                  uint32_t* __restrict__ wir)
{
    int bx = blockIdx.x;
    if (bx < 72) {
        int idx = bx * 256 + threadIdx.x;
        if (idx < 18432) repack_wh(w1, (uint4*)wh1, idx);
    } else if (bx < 144) {
        int idx = (bx - 72) * 256 + threadIdx.x;
        if (idx < 18432) repack_wh(w2, (uint4*)wh2, idx);
    } else {
        int idx = (bx - 144) * 256 + threadIdx.x;
        if (idx >= 16 * 8 * 32) return;
        int lane = idx & 31;
        int ocg = (idx >> 5) & 7;
        int chunk = idx >> 8;
        int oc = ocg * 16 + (lane >> 2);
        int ic = chunk * 8 + (lane & 3);
        uint32_t* o = wir + (size_t)idx * 4;
        o[0] = f2tf32(wi[(size_t)oc * CHN + ic]);
        o[1] = f2tf32(wi[(size_t)(oc + 8) * CHN + ic]);
        o[2] = f2tf32(wi[(size_t)oc * CHN + ic + 4]);
        o[3] = f2tf32(wi[(size_t)(oc + 8) * CHN + ic + 4]);
    }
}

// ---------------- conv 3x3 via fp16 m16n8k16 ----------------------------------
// CTA 256 thr (8 warps): 128 oc x 128 px (8 rows x 16 cols); 8 chunks of 16 ic.
// smem: sW[2][2304] uint4 (73728 B) + sIn[2][2880] half (11520 B) = 85248 B
#define CONVH_SMEM 85248

template <bool FIRST>
__global__ __launch_bounds__(256, 2) void conv_fp16_kernel(const float* __restrict__ bias)
{
    extern __shared__ char smem[];
    uint4* sW = (uint4*)smem;                  // [2][2304]
    __half* sIn = (__half*)(smem + 73728);     // [2][10 rows][18 px][16 icperm]

    const int tid = threadIdx.x;
    const int lane = tid & 31;
    const int wid = tid >> 5;
    const int warpM = wid & 3;
    const int warpN = wid >> 2;
    const int lq = lane >> 2;
    const int lr = lane & 3;
    const int b = blockIdx.z;
    const int r0 = blockIdx.y * 8;
    const int c0 = blockIdx.x * 16;

    float acc[2][8][4];
#pragma unroll
    for (int m = 0; m < 2; m++)
#pragma unroll
        for (int j = 0; j < 8; j++)
#pragma unroll
            for (int e = 0; e < 4; e++) acc[m][j][e] = 0.f;

    const uint4* wsrc = (const uint4*)(FIRST ? g_wh1 : g_wh2);
    const float* ibase = (FIRST ? g_cat : g_buf1) + (size_t)b * CHN * NPIX;

    // element decomposition for staging: e = (k*10 + row)*18 + px, e < 2880
    auto ld12 = [&](int cc, float* v) {
#pragma unroll
        for (int i = 0; i < 12; i++) {
            int e = tid + i * 256;
            v[i] = 0.f;
            if (e < 2880) {
                int k = e / 180;
                int rem = e - k * 180;
                int row = rem / 18, px = rem - row * 18;
                int gr = r0 - 1 + row, gc = c0 - 1 + px;
                if ((unsigned)gr < 128u && (unsigned)gc < 128u)
                    v[i] = ibase[(size_t)(cc * 16 + k) * NPIX + gr * 128 + gc];
            }
        }
    };
    auto st12 = [&](int buf, const float* v) {
        __half* dst = sIn + buf * 2880;
#pragma unroll
        for (int i = 0; i < 12; i++) {
            int e = tid + i * 256;
            if (e < 2880) {
                int k = e / 180;
                int rem = e - k * 180;
                int row = rem / 18, px = rem - row * 18;
                dst[row * 288 + px * 16 + icpos(k)] = __float2half_rn(v[i]);
            }
        }
    };
    auto stw = [&](int buf, int cc) {
        const uint4* src = wsrc + (size_t)cc * 2304;
        uint4* dst = sW + buf * 2304;
#pragma unroll
        for (int i = 0; i < 9; i++) cp16(smem_u32(dst + tid + i * 256), src + tid + i * 256);
    };

    // prologue
    {
        float v[12];
        ld12(0, v);
        st12(0, v);
        stw(0, 0);
        CP_COMMIT();
    }

    for (int cc = 0; cc < 8; cc++) {
        CP_WAIT0();
        __syncthreads();   // buf cc&1 ready (weights + input)

        float v[12];
        if (cc < 7) {
            ld12(cc + 1, v);           // LDG early; STS after compute
            stw((cc + 1) & 1, cc + 1);
            CP_COMMIT();
        }

        const uint4* wb = sW + (cc & 1) * 2304;
        const __half* ib = sIn + (cc & 1) * 2880;
#pragma unroll
        for (int tap = 0; tap < 9; tap++) {
            const int dr = tap / 3, dc = tap % 3;
            uint4 a0 = wb[(tap * 8 + warpM * 2 + 0) * 32 + lane];
            uint4 a1 = wb[(tap * 8 + warpM * 2 + 1) * 32 + lane];
#pragma unroll
            for (int j = 0; j < 8; j++) {
                int row = warpN * 4 + (j >> 1) + dr;
                int slot = (j & 1) * 8 + lq + dc;
                uint2 bv = *(const uint2*)(ib + row * 288 + slot * 16 + lr * 4);
                mma_f16(acc[0][j], a0, bv.x, bv.y);
                mma_f16(acc[1][j], a1, bv.x, bv.y);
            }
        }

        if (cc < 7) st12((cc + 1) & 1, v);   // next-iter __syncthreads covers visibility
    }

    // ---- epilogue ----
#pragma unroll
    for (int m = 0; m < 2; m++) {
        int oc = warpM * 32 + m * 16 + lq;
        float bv0 = bias[oc], bv1 = bias[oc + 8];
#pragma unroll
        for (int j = 0; j < 8; j++) {
            int irow = r0 + warpN * 4 + (j >> 1);
            int icol = c0 + (j & 1) * 8 + lr * 2;
            size_t base0 = ((size_t)(b * CHN + oc) * 128 + irow) * 128 + icol;
            size_t base1 = base0 + (size_t)8 * NPIX;
            if (FIRST) {
                float2 v0, v1;
                v0.x = leakyf(acc[m][j][0] + bv0);
                v0.y = leakyf(acc[m][j][1] + bv0);
                v1.x = leakyf(acc[m][j][2] + bv1);
                v1.y = leakyf(acc[m][j][3] + bv1);
                *(float2*)(g_buf1 + base0) = v0;
                *(float2*)(g_buf1 + base1) = v1;
            } else {
                float2 p0 = *(const float2*)(g_feat + base0);
                float2 p1 = *(const float2*)(g_feat + base1);
                p0.x += leakyf(acc[m][j][0] + bv0);
                p0.y += leakyf(acc[m][j][1] + bv0);
                p1.x += leakyf(acc[m][j][2] + bv1);
                p1.y += leakyf(acc[m][j][3] + bv1);
                *(float2*)(g_feat + base0) = p0;
                *(float2*)(g_feat + base1) = p1;
            }
        }
    }
}

// ---------------- 1x1 conv via tf32 mma: g_feat = wi @ cat + bi --------------
__global__ __launch_bounds__(256) void gemm1x1_kernel(const float* __restrict__ bi)
{
    __shared__ float sB[2][8 * 136];
    const int tid = threadIdx.x;
    const int lane = tid & 31;
    const int wid = tid >> 5;
    const int warpM = wid & 3;
    const int warpN = wid >> 2;
    const int lq = lane >> 2;
    const int lr = lane & 3;
    const int b = blockIdx.y;
    const int px0 = blockIdx.x * 128;

    float acc[2][8][4];
#pragma unroll
    for (int m = 0; m < 2; m++)
#pragma unroll
        for (int j = 0; j < 8; j++)
#pragma unroll
            for (int e = 0; e < 4; e++) acc[m][j][e] = 0.f;

    const uint4* wsrc = (const uint4*)g_wir;
    {
        int ic = tid >> 5, q = tid & 31;
        cp16(smem_u32(&sB[0][ic * 136 + q * 4]),
             g_cat + ((size_t)(b * CHN + ic)) * NPIX + px0 + q * 4);
    }
    CP_COMMIT();

    for (int cc = 0; cc < 16; cc++) {
        if (cc < 15) {
            int ic = tid >> 5, q = tid & 31;
            cp16(smem_u32(&sB[(cc + 1) & 1][ic * 136 + q * 4]),
                 g_cat + ((size_t)(b * CHN + (cc + 1) * 8 + ic)) * NPIX + px0 + q * 4);
            CP_COMMIT();
            CP_WAIT1();
        } else {
            CP_WAIT0();
        }
        __syncthreads();

        const float* sBb = sB[cc & 1];
        uint4 wf0 = wsrc[(cc * 8 + warpM * 2 + 0) * 32 + lane];
        uint4 wf1 = wsrc[(cc * 8 + warpM * 2 + 1) * 32 + lane];
#pragma unroll
        for (int j = 0; j < 8; j++) {
            int pxb = warpN * 64 + j * 8 + lq;
            uint32_t b0 = __float_as_uint(sBb[lr * 136 + pxb]);
            uint32_t b1 = __float_as_uint(sBb[(lr + 4) * 136 + pxb]);
            mma_tf32(acc[0][j], wf0, b0, b1);
            mma_tf32(acc[1][j], wf1, b0, b1);
        }
        __syncthreads();
    }

#pragma unroll
    for (int m = 0; m < 2; m++) {
        int oc = warpM * 32 + m * 16 + lq;
        float b0 = bi[oc], b1 = bi[oc + 8];
#pragma unroll
        for (int j = 0; j < 8; j++) {
            int px = px0 + warpN * 64 + j * 8 + lr * 2;
            size_t base0 = ((size_t)(b * CHN + oc)) * NPIX + px;
            size_t base1 = base0 + (size_t)8 * NPIX;
            float2 v0, v1;
            v0.x = acc[m][j][0] + b0; v0.y = acc[m][j][1] + b0;
            v1.x = acc[m][j][2] + b1; v1.y = acc[m][j][3] + b1;
            *(float2*)(g_feat + base0) = v0;
            *(float2*)(g_feat + base1) = v1;
        }
    }
}

// ---------------- L1 row sums + in-place scale --------------------------------
__global__ void rowsum_scale_kernel()
{
    int bc = blockIdx.x;
    float* p = g_feat + (size_t)bc * NPIX;
    float s = 0.f;
    for (int i = threadIdx.x * 4; i < NPIX; i += 1024) {
        float4 v = *(const float4*)(p + i);
        s += fabsf(v.x) + fabsf(v.y) + fabsf(v.z) + fabsf(v.w);
    }
    __shared__ float red[256];
    red[threadIdx.x] = s;
    __syncthreads();
    for (int st = 128; st > 0; st >>= 1) {
        if (threadIdx.x < st) red[threadIdx.x] += red[threadIdx.x + st];
        __syncthreads();
    }
    float inv = 1.0f / (1e-6f + red[0]);
    for (int i = threadIdx.x * 4; i < NPIX; i += 1024) {
        float4 v = *(const float4*)(p + i);
        v.x *= inv; v.y *= inv; v.z *= inv; v.w *= inv;
        *(float4*)(p + i) = v;
    }
}

// ---------------- G = V V^T via tf32 mma, split-K -----------------------------
__global__ __launch_bounds__(256, 2) void gemmG_mma_kernel()
{
    __shared__ float sV[2][128 * 20];
    const int tid = threadIdx.x;
    const int lane = tid & 31;
    const int wid = tid >> 5;
    const int warpM = wid & 3;
    const int warpN = wid >> 2;
    const int lq = lane >> 2;
    const int lr = lane & 3;
    const int slice = blockIdx.x, b = blockIdx.y;
    const float* base = g_feat + (size_t)b * CHN * NPIX;
    const int k0g = slice * 256;

    float acc[2][8][4];
#pragma unroll
    for (int mi = 0; mi < 2; mi++)
#pragma unroll
        for (int nj = 0; nj < 8; nj++)
#pragma unroll
            for (int e = 0; e < 4; e++) acc[mi][nj][e] = 0.f;

    {
        int c = tid >> 1, q = tid & 1;
        cp16(smem_u32(&sV[0][c * 20 + q * 8]), base + (size_t)c * NPIX + k0g + q * 8);
        cp16(smem_u32(&sV[0][c * 20 + q * 8 + 4]), base + (size_t)c * NPIX + k0g + q * 8 + 4);
    }
    CP_COMMIT();

    for (int kc = 0; kc < 16; kc++) {
        if (kc < 15) {
            int c = tid >> 1, q = tid & 1;
            int kk = k0g + (kc + 1) * 16;
            cp16(smem_u32(&sV[(kc + 1) & 1][c * 20 + q * 8]), base + (size_t)c * NPIX + kk + q * 8);
            cp16(smem_u32(&sV[(kc + 1) & 1][c * 20 + q * 8 + 4]),
                 base + (size_t)c * NPIX + kk + q * 8 + 4);
            CP_COMMIT();
            CP_WAIT1();
        } else {
            CP_WAIT0();
        }
        __syncthreads();
        const float* sv = sV[kc & 1];
#pragma unroll
        for (int ks = 0; ks < 2; ks++) {
            int k = ks * 8;
            uint4 af[2];
#pragma unroll
            for (int mi = 0; mi < 2; mi++) {
                int m0 = warpM * 32 + mi * 16;
                af[mi].x = __float_as_uint(sv[(m0 + lq) * 20 + k + lr]);
                af[mi].y = __float_as_uint(sv[(m0 + lq + 8) * 20 + k + lr]);
                af[mi].z = __float_as_uint(sv[(m0 + lq) * 20 + k + lr + 4]);
                af[mi].w = __float_as_uint(sv[(m0 + lq + 8) * 20 + k + lr + 4]);
            }
#pragma unroll
            for (int nj = 0; nj < 8; nj++) {
                int n0 = warpN * 64 + nj * 8;
                uint32_t b0 = __float_as_uint(sv[(n0 + lq) * 20 + k + lr]);
                uint32_t b1 = __float_as_uint(sv[(n0 + lq) * 20 + k + lr + 4]);
                mma_tf32(acc[0][nj], af[0], b0, b1);
                mma_tf32(acc[1][nj], af[1], b0, b1);
            }
        }
        __syncthreads();
    }

    float* outp = g_gpart + ((size_t)slice * BATCH + b) * CHN * CHN;
#pragma unroll
    for (int mi = 0; mi < 2; mi++) {
        int m0 = warpM * 32 + mi * 16 + lq;
#pragma unroll
        for (int nj = 0; nj < 8; nj++) {
            int n = warpN * 64 + nj * 8 + lr * 2;
            *(float2*)(outp + m0 * 128 + n) = make_float2(acc[mi][nj][0], acc[mi][nj][1]);
            *(float2*)(outp + (m0 + 8) * 128 + n) = make_float2(acc[mi][nj][2], acc[mi][nj][3]);
        }
    }
}

__global__ void reduceG_kernel()
{
    int o = blockIdx.x * 256 + threadIdx.x;
    float s = 0.f;
    for (int sl = 0; sl < NSLICE; sl++)
        s += g_gpart[(size_t)sl * (BATCH * CHN * CHN) + o];
    g_G[o] = s;
}

// ---------------- t = V @ x1^T via tf32 mma, split-K --------------------------
__global__ __launch_bounds__(256, 2) void gemmT_mma_kernel()
{
    __shared__ float sV[2][128 * 20];
    __shared__ float sX[2][64 * 20];
    const int tid = threadIdx.x;
    const int lane = tid & 31;
    const int wid = tid >> 5;
    const int warpM = wid & 3;
    const int warpN = wid >> 2;
    const int lq = lane >> 2;
    const int lr = lane & 3;
    const int slice = blockIdx.x, b = blockIdx.y;
    const float* vbase = g_feat + (size_t)b * CHN * NPIX;
    const float* xbase = g_cat + (size_t)b * CHN * NPIX;
    const int k0g = slice * 256;

    float acc[2][4][4];
#pragma unroll
    for (int mi = 0; mi < 2; mi++)
#pragma unroll
        for (int nj = 0; nj < 4; nj++)
#pragma unroll
            for (int e = 0; e < 4; e++) acc[mi][nj][e] = 0.f;

    auto stage = [&](int buf, int kc) {
        int kk = k0g + kc * 16;
        int c = tid >> 1, q = tid & 1;
        cp16(smem_u32(&sV[buf][c * 20 + q * 8]), vbase + (size_t)c * NPIX + kk + q * 8);
        cp16(smem_u32(&sV[buf][c * 20 + q * 8 + 4]), vbase + (size_t)c * NPIX + kk + q * 8 + 4);
        int m = tid >> 2, q2 = tid & 3;
        cp16(smem_u32(&sX[buf][m * 20 + q2 * 4]), xbase + (size_t)m * NPIX + kk + q2 * 4);
    };

    stage(0, 0);
    CP_COMMIT();

    for (int kc = 0; kc < 16; kc++) {
        if (kc < 15) {
            stage((kc + 1) & 1, kc + 1);
            CP_COMMIT();
            CP_WAIT1();
        } else {
            CP_WAIT0();
        }
        __syncthreads();
        const float* sv = sV[kc & 1];
        const float* sx = sX[kc & 1];
#pragma unroll
        for (int ks = 0; ks < 2; ks++) {
            int k = ks * 8;
            uint4 af[2];
#pragma unroll
            for (int mi = 0; mi < 2; mi++) {
                int m0 = warpM * 32 + mi * 16;
                af[mi].x = __float_as_uint(sv[(m0 + lq) * 20 + k + lr]);
                af[mi].y = __float_as_uint(sv[(m0 + lq + 8) * 20 + k + lr]);
                af[mi].z = __float_as_uint(sv[(m0 + lq) * 20 + k + lr + 4]);
                af[mi].w = __float_as_uint(sv[(m0 + lq + 8) * 20 + k + lr + 4]);
            }
#pragma unroll
            for (int nj = 0; nj < 4; nj++) {
                int n0 = warpN * 32 + nj * 8;
                uint32_t b0 = __float_as_uint(sx[(n0 + lq) * 20 + k + lr]);
                uint32_t b1 = __float_as_uint(sx[(n0 + lq) * 20 + k + lr + 4]);
                mma_tf32(acc[0][nj], af[0], b0, b1);
                mma_tf32(acc[1][nj], af[1], b0, b1);
            }
        }
        __syncthreads();
    }

    float* outp = g_tpart + ((size_t)slice * BATCH + b) * CHN * 64;
#pragma unroll
    for (int mi = 0; mi < 2; mi++) {
        int m0 = warpM * 32 + mi * 16 + lq;
#pragma unroll
        for (int nj = 0; nj < 4; nj++) {
            int n = warpN * 32 + nj * 8 + lr * 2;
            *(float2*)(outp + m0 * 64 + n) = make_float2(acc[mi][nj][0], acc[mi][nj][1]);
            *(float2*)(outp + (m0 + 8) * 64 + n) = make_float2(acc[mi][nj][2], acc[mi][nj][3]);
        }
    }
}

// ---------------- solve: [G | t] -> G^{-1} t, in shared memory ---------------
__global__ __launch_bounds__(768) void solve_kernel()
{
    extern __shared__ float sA[];  // [128][192]
    __shared__ float fcol[128];
    __shared__ float prow[192];
    const int b = blockIdx.x, tid = threadIdx.x;

    for (int i = tid; i < 128 * 128; i += 768) {
        int r = i >> 7, c = i & 127;
        sA[r * 192 + c] = g_G[(size_t)b * CHN * CHN + i];
    }
    for (int e = tid; e < 128 * 64; e += 768) {
        float s = 0.f;
        for (int sl = 0; sl < NSLICE; sl++)
            s += g_tpart[((size_t)sl * BATCH + b) * CHN * 64 + e];
        sA[(e >> 6) * 192 + 128 + (e & 63)] = s;
    }
    __syncthreads();

    const int j = tid % 192, g = tid / 192;
    for (int p = 0; p < 128; p++) {
        if (g == 0) {
            float piv = sA[p * 192 + p];
            prow[j] = sA[p * 192 + j] * (1.0f / piv);
        } else if (g == 1 && j < 128) {
            fcol[j] = (j == p) ? 0.f : sA[j * 192 + p];
        }
        __syncthreads();
        float pr = prow[j];
        const int i0 = g * 32;
#pragma unroll 4
        for (int i = i0; i < i0 + 32; i++) {
            float v = sA[i * 192 + j] - fcol[i] * pr;
            if (i == p) v = pr;
            sA[i * 192 + j] = v;
        }
        __syncthreads();
    }

    for (int e = tid; e < 128 * 64; e += 768)
        g_t2[(size_t)b * CHN * 64 + e] = sA[(e >> 6) * 192 + 128 + (e & 63)];
}

// ---------------- proj via tf32 mma -------------------------------------------
#define PROJ_SMEM (128 * 72 * 4 + 2 * 8 * 264 * 4)
__global__ __launch_bounds__(256, 2) void proj_mma_kernel(float* __restrict__ out)
{
    extern __shared__ float psm[];
    float* st2 = psm;                 // [128][72]
    float* sVc = psm + 128 * 72;      // [2][8][264]

    const int tid = threadIdx.x;
    const int lane = tid & 31;
    const int wid = tid >> 5;
    const int lq = lane >> 2;
    const int lr = lane & 3;
    const int b = blockIdx.y;
    const int n0cta = blockIdx.x * 256;
    const float* Vb = g_feat + (size_t)b * CHN * NPIX;

    {
        int e4 = tid;
        for (int i = 0; i < 8; i++, e4 += 256) {
            int c = e4 >> 4, mq = e4 & 15;
            cp16(smem_u32(st2 + c * 72 + mq * 4), g_t2 + (size_t)b * CHN * 64 + c * 64 + mq * 4);
        }
    }
    auto stageV = [&](int buf, int cc) {
        int r = tid >> 6, q = tid & 63;
        cp16(smem_u32(sVc + buf * 8 * 264 + r * 264 + q * 4),
             Vb + (size_t)(cc * 8 + r) * NPIX + n0cta + q * 4);
        cp16(smem_u32(sVc + buf * 8 * 264 + (r + 4) * 264 + q * 4),
             Vb + (size_t)(cc * 8 + r + 4) * NPIX + n0cta + q * 4);
    };
    stageV(0, 0);
    CP_COMMIT();

    float acc[4][4][4];
#pragma unroll
    for (int mi = 0; mi < 4; mi++)
#pragma unroll
        for (int nj = 0; nj < 4; nj++)
#pragma unroll
            for (int e = 0; e < 4; e++) acc[mi][nj][e] = 0.f;

    for (int cc = 0; cc < 16; cc++) {
        if (cc < 15) {
            stageV((cc + 1) & 1, cc + 1);
            CP_COMMIT();
            CP_WAIT1();
        } else {
            CP_WAIT0();
        }
        __syncthreads();
        const float* sv = sVc + (cc & 1) * 8 * 264;
        uint4 af[4];
#pragma unroll
        for (int mi = 0; mi < 4; mi++) {
            int m0 = mi * 16;
            int c0 = cc * 8;
            af[mi].x = __float_as_uint(st2[(c0 + lr) * 72 + m0 + lq]);
            af[mi].y = __float_as_uint(st2[(c0 + lr) * 72 + m0 + lq + 8]);
            af[mi].z = __float_as_uint(st2[(c0 + lr + 4) * 72 + m0 + lq]);
            af[mi].w = __float_as_uint(st2[(c0 + lr + 4) * 72 + m0 + lq + 8]);
        }
#pragma unroll
        for (int nj = 0; nj < 4; nj++) {
            int n0 = wid * 32 + nj * 8;
            uint32_t b0 = __float_as_uint(sv[lr * 264 + n0 + lq]);
            uint32_t b1 = __float_as_uint(sv[(lr + 4) * 264 + n0 + lq]);
#pragma unroll
            for (int mi = 0; mi < 4; mi++) mma_tf32(acc[mi][nj], af[mi], b0, b1);
        }
        __syncthreads();
    }

#pragma unroll
    for (int mi = 0; mi < 4; mi++) {
        int m0 = mi * 16 + lq;
#pragma unroll
        for (int nj = 0; nj < 4; nj++) {
            int n = n0cta + wid * 32 + nj * 8 + lr * 2;
            *(float2*)(out + ((size_t)(b * 64 + m0)) * NPIX + n) =
                make_float2(acc[mi][nj][0], acc[mi][nj][1]);
            *(float2*)(out + ((size_t)(b * 64 + m0 + 8)) * NPIX + n) =
                make_float2(acc[mi][nj][2], acc[mi][nj][3]);
        }
    }
}

// ---------------- launch -----------------------------------------------------
extern "C" void kernel_launch(void* const* d_in, const int* in_sizes, int n_in,
                              void* d_out, int out_size)
{
    const float* x1 = (const float*)d_in[0];
    const float* x2 = (const float*)d_in[1];
    const float* w1 = (const float*)d_in[2];
    const float* b1 = (const float*)d_in[3];
    const float* w2 = (const float*)d_in[4];
    const float* b2 = (const float*)d_in[5];
    const float* wi = (const float*)d_in[6];
    const float* bi = (const float*)d_in[7];
    float* out = (float*)d_out;

    static bool attr_done = false;
    if (!attr_done) {
        cudaFuncSetAttribute(solve_kernel, cudaFuncAttributeMaxDynamicSharedMemorySize,
                             128 * 192 * sizeof(float));
        cudaFuncSetAttribute(conv_fp16_kernel<true>,
                             cudaFuncAttributeMaxDynamicSharedMemorySize, CONVH_SMEM);
        cudaFuncSetAttribute(conv_fp16_kernel<false>,
                             cudaFuncAttributeMaxDynamicSharedMemorySize, CONVH_SMEM);
        cudaFuncSetAttribute(proj_mma_kernel,
                             cudaFuncAttributeMaxDynamicSharedMemorySize, PROJ_SMEM);
        attr_done = true;
    }

    uint32_t* wh1;  cudaGetSymbolAddress((void**)&wh1, g_wh1);
    uint32_t* wh2;  cudaGetSymbolAddress((void**)&wh2, g_wh2);
    uint32_t* wir;  cudaGetSymbolAddress((void**)&wir, g_wir);

    prep_cat_kernel<<<8192, 256>>>(x1, x2);
    repack_all_kernel<<<160, 256>>>(w1, w2, wi, wh1, wh2, wir);

    dim3 cgrid(8, 16, 4);
    conv_fp16_kernel<true><<<cgrid, 256, CONVH_SMEM>>>(b1);
    gemm1x1_kernel<<<dim3(128, 4), 256>>>(bi);
    conv_fp16_kernel<false><<<cgrid, 256, CONVH_SMEM>>>(b2);

    rowsum_scale_kernel<<<512, 256>>>();
    gemmG_mma_kernel<<<dim3(NSLICE, BATCH), 256>>>();
    reduceG_kernel<<<256, 256>>>();
    gemmT_mma_kernel<<<dim3(NSLICE, BATCH), 256>>>();
    solve_kernel<<<BATCH, 768, 128 * 192 * sizeof(float)>>>();
    proj_mma_kernel<<<dim3(64, BATCH), 256, PROJ_SMEM>>>(out);
}

// round 8
// speedup vs baseline: 1.1618x; 1.0332x over previous
#include <cuda_runtime.h>
#include <cuda_fp16.h>
#include <cstdint>
#include <cstddef>

#define NPIX 16384
#define CHN 128
#define BATCH 4
#define NSLICE 64

// ---------------- scratch (device globals; no allocation allowed) -------------
__device__ float g_cat[BATCH * CHN * NPIX];           // tf32(x1) (ch<64 used by gemmT)
__device__ __align__(16) __half g_cath[BATCH * 8 * NPIX * 16];   // cat, fp16 interleaved
__device__ __align__(16) __half g_buf1h[BATCH * 8 * NPIX * 16];  // conv1 out, fp16 interleaved
__device__ float g_feat[BATCH * CHN * NPIX];          // 1x1 out, then feat, then V
__device__ float g_gpart[NSLICE * BATCH * CHN * CHN];
__device__ float g_G[BATCH * CHN * CHN];
__device__ float g_tpart[NSLICE * BATCH * CHN * 64];
__device__ float g_t2[BATCH * CHN * 64];
// fp16 conv weight fragments: [chunk8][tap9][mfrag8][lane32] uint4
__device__ uint32_t g_wh1[8 * 9 * 8 * 32 * 4];
__device__ uint32_t g_wh2[8 * 9 * 8 * 32 * 4];
__device__ uint32_t g_wih[8 * 8 * 32 * 4];            // 1x1 fp16 fragments

__device__ __forceinline__ float leakyf(float v) { return v >= 0.f ? v : 0.2f * v; }

__device__ __forceinline__ uint32_t f2tf32(float f) {
    uint32_t o;
    asm("cvt.rna.tf32.f32 %0, %1;" : "=r"(o) : "f"(f));
    return o;
}
__device__ __forceinline__ float tf32r(float f) { return __uint_as_float(f2tf32(f)); }

__device__ __forceinline__ void mma_tf32(float* acc, const uint4& a, uint32_t b0, uint32_t b1) {
    asm volatile(
        "mma.sync.aligned.m16n8k8.row.col.f32.tf32.tf32.f32 "
        "{%0,%1,%2,%3}, {%4,%5,%6,%7}, {%8,%9}, {%0,%1,%2,%3};"
        : "+f"(acc[0]), "+f"(acc[1]), "+f"(acc[2]), "+f"(acc[3])
        : "r"(a.x), "r"(a.y), "r"(a.z), "r"(a.w), "r"(b0), "r"(b1));
}
__device__ __forceinline__ void mma_f16(float* acc, const uint4& a, uint32_t b0, uint32_t b1) {
    asm volatile(
        "mma.sync.aligned.m16n8k16.row.col.f32.f16.f16.f32 "
        "{%0,%1,%2,%3}, {%4,%5,%6,%7}, {%8,%9}, {%0,%1,%2,%3};"
        : "+f"(acc[0]), "+f"(acc[1]), "+f"(acc[2]), "+f"(acc[3])
        : "r"(a.x), "r"(a.y), "r"(a.z), "r"(a.w), "r"(b0), "r"(b1));
}

__device__ __forceinline__ uint32_t smem_u32(const void* p) {
    return (uint32_t)__cvta_generic_to_shared(p);
}
__device__ __forceinline__ void cp16(uint32_t s, const void* g) {
    asm volatile("cp.async.cg.shared.global [%0], [%1], 16;" :: "r"(s), "l"(g));
}
__device__ __forceinline__ void cp16z(uint32_t s, const void* g, int valid16) {
    asm volatile("cp.async.cg.shared.global [%0], [%1], 16, %2;"
                 :: "r"(s), "l"(g), "r"(valid16));
}
#define CP_COMMIT() asm volatile("cp.async.commit_group;")
#define CP_WAIT1() asm volatile("cp.async.wait_group 1;")
#define CP_WAIT0() asm volatile("cp.async.wait_group 0;")

__device__ __forceinline__ uint32_t pack_h2(float lo, float hi) {
    __half2 h = __floats2half2_rn(lo, hi);
    return *(uint32_t*)&h;
}
// permuted ic position inside 16-ic group (matches m16n8k16 B-fragment order)
__device__ __forceinline__ int icpos(int k) {
    return (k < 8) ? ((k >> 1) * 4 + (k & 1)) : (((k - 8) >> 1) * 4 + 2 + (k & 1));
}

// ---------------- prep: concat -> fp16 interleaved (+tf32 x1 for gemmT) -------
__global__ void prep_cat_kernel(const float* __restrict__ x1, const float* __restrict__ x2)
{
    int i4 = blockIdx.x * 256 + threadIdx.x;
    if (i4 >= (BATCH * CHN * NPIX) / 4) return;
    size_t base = (size_t)i4 * 4;
    int b = (int)(base >> 21);
    int rem = (int)(base & ((1u << 21) - 1));
    int ic = rem >> 14;
    int n = rem & (NPIX - 1);
    const float* src = (ic < 64) ? x1 + ((size_t)(b * 64 + ic) << 14) + n
                                 : x2 + ((size_t)(b * 64 + ic - 64) << 14) + n;
    float4 v = *(const float4*)src;
    // fp16 interleaved
    int chunk = ic >> 4;
    int ip = icpos(ic & 15);
    __half* hd = g_cath + (((size_t)(b * 8 + chunk) * NPIX + n) << 4) + ip;
    hd[0] = __float2half_rn(v.x);
    hd[16] = __float2half_rn(v.y);
    hd[32] = __float2half_rn(v.z);
    hd[48] = __float2half_rn(v.w);
    // tf32 (only x1 channels, consumed by gemmT)
    if (ic < 64) {
        float4 t;
        t.x = tf32r(v.x); t.y = tf32r(v.y); t.z = tf32r(v.z); t.w = tf32r(v.w);
        *(float4*)(g_cat + base) = t;
    }
}

// ---------------- weight repack ----------------------------------------------
// fp16 conv frags: idx = ((chunk*9+tap)*8+mf)*32+lane
__device__ __forceinline__ void repack_wh(const float* __restrict__ w, uint4* __restrict__ out,
                                          int idx)
{
    int lane = idx & 31;
    int t = idx >> 5;
    int mf = t & 7;
    int t2 = t >> 3;
    int tap = t2 % 9;
    int chunk = t2 / 9;
    int lq = lane >> 2, lr = lane & 3;
    int oc0 = mf * 16 + lq, oc1 = oc0 + 8;
    int kb = chunk * 16;
    uint4 o;
    o.x = pack_h2(w[((size_t)oc0 * CHN + kb + 2 * lr) * 9 + tap],
                  w[((size_t)oc0 * CHN + kb + 2 * lr + 1) * 9 + tap]);
    o.y = pack_h2(w[((size_t)oc1 * CHN + kb + 2 * lr) * 9 + tap],
                  w[((size_t)oc1 * CHN + kb + 2 * lr + 1) * 9 + tap]);
    o.z = pack_h2(w[((size_t)oc0 * CHN + kb + 8 + 2 * lr) * 9 + tap],
                  w[((size_t)oc0 * CHN + kb + 9 + 2 * lr) * 9 + tap]);
    o.w = pack_h2(w[((size_t)oc1 * CHN + kb + 8 + 2 * lr) * 9 + tap],
                  w[((size_t)oc1 * CHN + kb + 9 + 2 * lr) * 9 + tap]);
    out[idx] = o;
}

__global__ void repack_all_kernel(const float* __restrict__ w1, const float* __restrict__ w2,
                                  const float* __restrict__ wi,
                                  uint32_t* __restrict__ wh1, uint32_t* __restrict__ wh2,
                                  uint32_t* __restrict__ wih)
{
    int bx = blockIdx.x;
    if (bx < 72) {
        int idx = bx * 256 + threadIdx.x;
        if (idx < 18432) repack_wh(w1, (uint4*)wh1, idx);
    } else if (bx < 144) {
        int idx = (bx - 72) * 256 + threadIdx.x;
        if (idx < 18432) repack_wh(w2, (uint4*)wh2, idx);
    } else {
        int idx = (bx - 144) * 256 + threadIdx.x;
        if (idx >= 2048) return;  // 8 chunks * 8 mf * 32 lanes
        int lane = idx & 31;
        int t = idx >> 5;
        int mf = t & 7;
        int chunk = t >> 3;
        int lq = lane >> 2, lr = lane & 3;
        int oc0 = mf * 16 + lq, oc1 = oc0 + 8;
        int kb = chunk * 16;
        uint4 o;
        o.x = pack_h2(wi[(size_t)oc0 * CHN + kb + 2 * lr], wi[(size_t)oc0 * CHN + kb + 2 * lr + 1]);
        o.y = pack_h2(wi[(size_t)oc1 * CHN + kb + 2 * lr], wi[(size_t)oc1 * CHN + kb + 2 * lr + 1]);
        o.z = pack_h2(wi[(size_t)oc0 * CHN + kb + 8 + 2 * lr], wi[(size_t)oc0 * CHN + kb + 9 + 2 * lr]);
        o.w = pack_h2(wi[(size_t)oc1 * CHN + kb + 8 + 2 * lr], wi[(size_t)oc1 * CHN + kb + 9 + 2 * lr]);
        ((uint4*)wih)[idx] = o;
    }
}

// ---------------- conv 3x3 via fp16 m16n8k16, pure cp.async staging ----------
// CTA 256 thr (8 warps): 128 oc x 128 px (8 rows x 16 cols); 8 chunks of 16 ic.
// smem: sW[2][2304] uint4 (73728 B) + sIn[2][2880] half (11520 B) = 85248 B
#define CONVH_SMEM 85248

template <bool FIRST>
__global__ __launch_bounds__(256, 2) void conv_fp16_kernel(const float* __restrict__ bias)
{
    extern __shared__ char smem[];
    uint4* sW = (uint4*)smem;                  // [2][2304]
    __half* sIn = (__half*)(smem + 73728);     // [2][10 rows][18 px][16 icperm]

    const int tid = threadIdx.x;
    const int lane = tid & 31;
    const int wid = tid >> 5;
    const int warpM = wid & 3;
    const int warpN = wid >> 2;
    const int lq = lane >> 2;
    const int lr = lane & 3;
    const int b = blockIdx.z;
    const int r0 = blockIdx.y * 8;
    const int c0 = blockIdx.x * 16;

    float acc[2][8][4];
#pragma unroll
    for (int m = 0; m < 2; m++)
#pragma unroll
        for (int j = 0; j < 8; j++)
#pragma unroll
            for (int e = 0; e < 4; e++) acc[m][j][e] = 0.f;

    const uint4* wsrc = (const uint4*)(FIRST ? g_wh1 : g_wh2);
    const __half* ibase = (FIRST ? g_cath : g_buf1h) + ((size_t)b * 8 * NPIX << 4);

    auto stw = [&](int buf, int cc) {
        const uint4* src = wsrc + (size_t)cc * 2304;
        uint4* dst = sW + buf * 2304;
#pragma unroll
        for (int i = 0; i < 9; i++) cp16(smem_u32(dst + tid + i * 256), src + tid + i * 256);
    };
    auto stin = [&](int buf, int cc) {
        const __half* src = ibase + ((size_t)cc * NPIX << 4);
        __half* dst = sIn + buf * 2880;
        for (int i = tid; i < 360; i += 256) {
            int row = i / 36;
            int p2 = i - row * 36;
            int px = p2 >> 1, hp = p2 & 1;
            int gr = r0 - 1 + row, gc = c0 - 1 + px;
            bool ok = ((unsigned)gr < 128u) && ((unsigned)gc < 128u);
            const __half* g = src + (((size_t)(ok ? gr * 128 + gc : 0)) << 4) + hp * 8;
            cp16z(smem_u32(dst + row * 288 + px * 16 + hp * 8), g, ok ? 16 : 0);
        }
    };

    stin(0, 0);
    stw(0, 0);
    CP_COMMIT();

    for (int cc = 0; cc < 8; cc++) {
        if (cc < 7) {
            stin((cc + 1) & 1, cc + 1);
            stw((cc + 1) & 1, cc + 1);
            CP_COMMIT();
            CP_WAIT1();
        } else {
            CP_WAIT0();
        }
        __syncthreads();

        const uint4* wb = sW + (cc & 1) * 2304;
        const __half* ib = sIn + (cc & 1) * 2880;
#pragma unroll
        for (int tap = 0; tap < 9; tap++) {
            const int dr = tap / 3, dc = tap % 3;
            uint4 a0 = wb[(tap * 8 + warpM * 2 + 0) * 32 + lane];
            uint4 a1 = wb[(tap * 8 + warpM * 2 + 1) * 32 + lane];
#pragma unroll
            for (int j = 0; j < 8; j++) {
                int row = warpN * 4 + (j >> 1) + dr;
                int slot = (j & 1) * 8 + lq + dc;
                uint2 bv = *(const uint2*)(ib + row * 288 + slot * 16 + lr * 4);
                mma_f16(acc[0][j], a0, bv.x, bv.y);
                mma_f16(acc[1][j], a1, bv.x, bv.y);
            }
        }
        __syncthreads();
    }

    // ---- epilogue ----
#pragma unroll
    for (int m = 0; m < 2; m++) {
        int oc = warpM * 32 + m * 16 + lq;       // oc&15 == lq
        float bv0 = bias[oc], bv1 = bias[oc + 8];
        if (FIRST) {
            const int chunk = warpM * 2 + m;
            const int ip0 = icpos(lq), ip1 = icpos(lq + 8);
            __half* hb = g_buf1h + (((size_t)(b * 8 + chunk) * NPIX) << 4);
#pragma unroll
            for (int j = 0; j < 8; j++) {
                int pix = (r0 + warpN * 4 + (j >> 1)) * 128 + c0 + (j & 1) * 8 + lr * 2;
                __half* p = hb + ((size_t)pix << 4);
                p[ip0] = __float2half_rn(leakyf(acc[m][j][0] + bv0));
                p[16 + ip0] = __float2half_rn(leakyf(acc[m][j][1] + bv0));
                p[ip1] = __float2half_rn(leakyf(acc[m][j][2] + bv1));
                p[16 + ip1] = __float2half_rn(leakyf(acc[m][j][3] + bv1));
            }
        } else {
#pragma unroll
            for (int j = 0; j < 8; j++) {
                int irow = r0 + warpN * 4 + (j >> 1);
                int icol = c0 + (j & 1) * 8 + lr * 2;
                size_t base0 = ((size_t)(b * CHN + oc) * 128 + irow) * 128 + icol;
                size_t base1 = base0 + (size_t)8 * NPIX;
                float2 p0 = *(const float2*)(g_feat + base0);
                float2 p1 = *(const float2*)(g_feat + base1);
                p0.x += leakyf(acc[m][j][0] + bv0);
                p0.y += leakyf(acc[m][j][1] + bv0);
                p1.x += leakyf(acc[m][j][2] + bv1);
                p1.y += leakyf(acc[m][j][3] + bv1);
                *(float2*)(g_feat + base0) = p0;
                *(float2*)(g_feat + base1) = p1;
            }
        }
    }
}

// ---------------- 1x1 conv via fp16 m16n8k16 (reuses g_cath) ------------------
__global__ __launch_bounds__(256) void gemm1x1h_kernel(const float* __restrict__ bi)
{
    __shared__ uint4 sW1[2][256];
    __shared__ __half sB[2][2048];   // [row8][px16][16icp]

    const int tid = threadIdx.x;
    const int lane = tid & 31;
    const int wid = tid >> 5;
    const int warpM = wid & 3;
    const int warpN = wid >> 2;
    const int lq = lane >> 2;
    const int lr = lane & 3;
    const int b = blockIdx.z;
    const int r0 = blockIdx.y * 8;
    const int c0 = blockIdx.x * 16;

    float acc[2][8][4];
#pragma unroll
    for (int m = 0; m < 2; m++)
#pragma unroll
        for (int j = 0; j < 8; j++)
#pragma unroll
            for (int e = 0; e < 4; e++) acc[m][j][e] = 0.f;

    const __half* ibase = g_cath + ((size_t)b * 8 * NPIX << 4);

    auto stage = [&](int buf, int cc) {
        int hp = tid & 1;
        int pl = tid >> 1;            // 0..127
        int row = pl >> 4, px = pl & 15;
        int pix = (r0 + row) * 128 + c0 + px;
        cp16(smem_u32(&sB[buf][(row * 16 + px) * 16 + hp * 8]),
             ibase + ((size_t)cc * NPIX << 4) + ((size_t)pix << 4) + hp * 8);
        cp16(smem_u32(&sW1[buf][tid]), ((const uint4*)g_wih) + cc * 256 + tid);
    };

    stage(0, 0);
    CP_COMMIT();

    for (int cc = 0; cc < 8; cc++) {
        if (cc < 7) {
            stage((cc + 1) & 1, cc + 1);
            CP_COMMIT();
            CP_WAIT1();
        } else {
            CP_WAIT0();
        }
        __syncthreads();

        uint4 a0 = sW1[cc & 1][(warpM * 2 + 0) * 32 + lane];
        uint4 a1 = sW1[cc & 1][(warpM * 2 + 1) * 32 + lane];
        const __half* ib = sB[cc & 1];
#pragma unroll
        for (int j = 0; j < 8; j++) {
            int row = warpN * 4 + (j >> 1);
            int slot = (j & 1) * 8 + lq;
            uint2 bv = *(const uint2*)(ib + (row * 16 + slot) * 16 + lr * 4);
            mma_f16(acc[0][j], a0, bv.x, bv.y);
            mma_f16(acc[1][j], a1, bv.x, bv.y);
        }
        __syncthreads();
    }

#pragma unroll
    for (int m = 0; m < 2; m++) {
        int oc = warpM * 32 + m * 16 + lq;
        float b0 = bi[oc], b1 = bi[oc + 8];
#pragma unroll
        for (int j = 0; j < 8; j++) {
            int irow = r0 + warpN * 4 + (j >> 1);
            int icol = c0 + (j & 1) * 8 + lr * 2;
            size_t base0 = ((size_t)(b * CHN + oc) * 128 + irow) * 128 + icol;
            size_t base1 = base0 + (size_t)8 * NPIX;
            *(float2*)(g_feat + base0) = make_float2(acc[m][j][0] + b0, acc[m][j][1] + b0);
            *(float2*)(g_feat + base1) = make_float2(acc[m][j][2] + b1, acc[m][j][3] + b1);
        }
    }
}

// ---------------- L1 row sums + in-place scale --------------------------------
__global__ void rowsum_scale_kernel()
{
    int bc = blockIdx.x;
    float* p = g_feat + (size_t)bc * NPIX;
    float s = 0.f;
    for (int i = threadIdx.x * 4; i < NPIX; i += 1024) {
        float4 v = *(const float4*)(p + i);
        s += fabsf(v.x) + fabsf(v.y) + fabsf(v.z) + fabsf(v.w);
    }
    __shared__ float red[256];
    red[threadIdx.x] = s;
    __syncthreads();
    for (int st = 128; st > 0; st >>= 1) {
        if (threadIdx.x < st) red[threadIdx.x] += red[threadIdx.x + st];
        __syncthreads();
    }
    float inv = 1.0f / (1e-6f + red[0]);
    for (int i = threadIdx.x * 4; i < NPIX; i += 1024) {
        float4 v = *(const float4*)(p + i);
        v.x *= inv; v.y *= inv; v.z *= inv; v.w *= inv;
        *(float4*)(p + i) = v;
    }
}

// ---------------- G = V V^T via tf32 mma, split-K -----------------------------
__global__ __launch_bounds__(256, 2) void gemmG_mma_kernel()
{
    __shared__ float sV[2][128 * 20];
    const int tid = threadIdx.x;
    const int lane = tid & 31;
    const int wid = tid >> 5;
    const int warpM = wid & 3;
    const int warpN = wid >> 2;
    const int lq = lane >> 2;
    const int lr = lane & 3;
    const int slice = blockIdx.x, b = blockIdx.y;
    const float* base = g_feat + (size_t)b * CHN * NPIX;
    const int k0g = slice * 256;

    float acc[2][8][4];
#pragma unroll
    for (int mi = 0; mi < 2; mi++)
#pragma unroll
        for (int nj = 0; nj < 8; nj++)
#pragma unroll
            for (int e = 0; e < 4; e++) acc[mi][nj][e] = 0.f;

    {
        int c = tid >> 1, q = tid & 1;
        cp16(smem_u32(&sV[0][c * 20 + q * 8]), base + (size_t)c * NPIX + k0g + q * 8);
        cp16(smem_u32(&sV[0][c * 20 + q * 8 + 4]), base + (size_t)c * NPIX + k0g + q * 8 + 4);
    }
    CP_COMMIT();

    for (int kc = 0; kc < 16; kc++) {
        if (kc < 15) {
            int c = tid >> 1, q = tid & 1;
            int kk = k0g + (kc + 1) * 16;
            cp16(smem_u32(&sV[(kc + 1) & 1][c * 20 + q * 8]), base + (size_t)c * NPIX + kk + q * 8);
            cp16(smem_u32(&sV[(kc + 1) & 1][c * 20 + q * 8 + 4]),
                 base + (size_t)c * NPIX + kk + q * 8 + 4);
            CP_COMMIT();
            CP_WAIT1();
        } else {
            CP_WAIT0();
        }
        __syncthreads();
        const float* sv = sV[kc & 1];
#pragma unroll
        for (int ks = 0; ks < 2; ks++) {
            int k = ks * 8;
            uint4 af[2];
#pragma unroll
            for (int mi = 0; mi < 2; mi++) {
                int m0 = warpM * 32 + mi * 16;
                af[mi].x = __float_as_uint(sv[(m0 + lq) * 20 + k + lr]);
                af[mi].y = __float_as_uint(sv[(m0 + lq + 8) * 20 + k + lr]);
                af[mi].z = __float_as_uint(sv[(m0 + lq) * 20 + k + lr + 4]);
                af[mi].w = __float_as_uint(sv[(m0 + lq + 8) * 20 + k + lr + 4]);
            }
#pragma unroll
            for (int nj = 0; nj < 8; nj++) {
                int n0 = warpN * 64 + nj * 8;
                uint32_t b0 = __float_as_uint(sv[(n0 + lq) * 20 + k + lr]);
                uint32_t b1 = __float_as_uint(sv[(n0 + lq) * 20 + k + lr + 4]);
                mma_tf32(acc[0][nj], af[0], b0, b1);
                mma_tf32(acc[1][nj], af[1], b0, b1);
            }
        }
        __syncthreads();
    }

    float* outp = g_gpart + ((size_t)slice * BATCH + b) * CHN * CHN;
#pragma unroll
    for (int mi = 0; mi < 2; mi++) {
        int m0 = warpM * 32 + mi * 16 + lq;
#pragma unroll
        for (int nj = 0; nj < 8; nj++) {
            int n = warpN * 64 + nj * 8 + lr * 2;
            *(float2*)(outp + m0 * 128 + n) = make_float2(acc[mi][nj][0], acc[mi][nj][1]);
            *(float2*)(outp + (m0 + 8) * 128 + n) = make_float2(acc[mi][nj][2], acc[mi][nj][3]);
        }
    }
}

__global__ void reduceG_kernel()
{
    int o = blockIdx.x * 256 + threadIdx.x;
    float s = 0.f;
    for (int sl = 0; sl < NSLICE; sl++)
        s += g_gpart[(size_t)sl * (BATCH * CHN * CHN) + o];
    g_G[o] = s;
}

// ---------------- t = V @ x1^T via tf32 mma, split-K --------------------------
__global__ __launch_bounds__(256, 2) void gemmT_mma_kernel()
{
    __shared__ float sV[2][128 * 20];
    __shared__ float sX[2][64 * 20];
    const int tid = threadIdx.x;
    const int lane = tid & 31;
    const int wid = tid >> 5;
    const int warpM = wid & 3;
    const int warpN = wid >> 2;
    const int lq = lane >> 2;
    const int lr = lane & 3;
    const int slice = blockIdx.x, b = blockIdx.y;
    const float* vbase = g_feat + (size_t)b * CHN * NPIX;
    const float* xbase = g_cat + (size_t)b * CHN * NPIX;
    const int k0g = slice * 256;

    float acc[2][4][4];
#pragma unroll
    for (int mi = 0; mi < 2; mi++)
#pragma unroll
        for (int nj = 0; nj < 4; nj++)
#pragma unroll
            for (int e = 0; e < 4; e++) acc[mi][nj][e] = 0.f;

    auto stage = [&](int buf, int kc) {
        int kk = k0g + kc * 16;
        int c = tid >> 1, q = tid & 1;
        cp16(smem_u32(&sV[buf][c * 20 + q * 8]), vbase + (size_t)c * NPIX + kk + q * 8);
        cp16(smem_u32(&sV[buf][c * 20 + q * 8 + 4]), vbase + (size_t)c * NPIX + kk + q * 8 + 4);
        int m = tid >> 2, q2 = tid & 3;
        cp16(smem_u32(&sX[buf][m * 20 + q2 * 4]), xbase + (size_t)m * NPIX + kk + q2 * 4);
    };

    stage(0, 0);
    CP_COMMIT();

    for (int kc = 0; kc < 16; kc++) {
        if (kc < 15) {
            stage((kc + 1) & 1, kc + 1);
            CP_COMMIT();
            CP_WAIT1();
        } else {
            CP_WAIT0();
        }
        __syncthreads();
        const float* sv = sV[kc & 1];
        const float* sx = sX[kc & 1];
#pragma unroll
        for (int ks = 0; ks < 2; ks++) {
            int k = ks * 8;
            uint4 af[2];
#pragma unroll
            for (int mi = 0; mi < 2; mi++) {
                int m0 = warpM * 32 + mi * 16;
                af[mi].x = __float_as_uint(sv[(m0 + lq) * 20 + k + lr]);
                af[mi].y = __float_as_uint(sv[(m0 + lq + 8) * 20 + k + lr]);
                af[mi].z = __float_as_uint(sv[(m0 + lq) * 20 + k + lr + 4]);
                af[mi].w = __float_as_uint(sv[(m0 + lq + 8) * 20 + k + lr + 4]);
            }
#pragma unroll
            for (int nj = 0; nj < 4; nj++) {
                int n0 = warpN * 32 + nj * 8;
                uint32_t b0 = __float_as_uint(sx[(n0 + lq) * 20 + k + lr]);
                uint32_t b1 = __float_as_uint(sx[(n0 + lq) * 20 + k + lr + 4]);
                mma_tf32(acc[0][nj], af[0], b0, b1);
                mma_tf32(acc[1][nj], af[1], b0, b1);
            }
        }
        __syncthreads();
    }

    float* outp = g_tpart + ((size_t)slice * BATCH + b) * CHN * 64;
#pragma unroll
    for (int mi = 0; mi < 2; mi++) {
        int m0 = warpM * 32 + mi * 16 + lq;
#pragma unroll
        for (int nj = 0; nj < 4; nj++) {
            int n = warpN * 32 + nj * 8 + lr * 2;
            *(float2*)(outp + m0 * 64 + n) = make_float2(acc[mi][nj][0], acc[mi][nj][1]);
            *(float2*)(outp + (m0 + 8) * 64 + n) = make_float2(acc[mi][nj][2], acc[mi][nj][3]);
        }
    }
}

// ---------------- solve: [G | t] -> G^{-1} t, in shared memory ---------------
__global__ __launch_bounds__(768) void solve_kernel()
{
    extern __shared__ float sA[];  // [128][192]
    __shared__ float fcol[128];
    __shared__ float prow[192];
    const int b = blockIdx.x, tid = threadIdx.x;

    for (int i = tid; i < 128 * 128; i += 768) {
        int r = i >> 7, c = i & 127;
        sA[r * 192 + c] = g_G[(size_t)b * CHN * CHN + i];
    }
    for (int e = tid; e < 128 * 64; e += 768) {
        float s = 0.f;
        for (int sl = 0; sl < NSLICE; sl++)
            s += g_tpart[((size_t)sl * BATCH + b) * CHN * 64 + e];
        sA[(e >> 6) * 192 + 128 + (e & 63)] = s;
    }
    __syncthreads();

    const int j = tid % 192, g = tid / 192;
    for (int p = 0; p < 128; p++) {
        if (g == 0) {
            float piv = sA[p * 192 + p];
            prow[j] = sA[p * 192 + j] * (1.0f / piv);
        } else if (g == 1 && j < 128) {
            fcol[j] = (j == p) ? 0.f : sA[j * 192 + p];
        }
        __syncthreads();
        float pr = prow[j];
        const int i0 = g * 32;
#pragma unroll 4
        for (int i = i0; i < i0 + 32; i++) {
            float v = sA[i * 192 + j] - fcol[i] * pr;
            if (i == p) v = pr;
            sA[i * 192 + j] = v;
        }
        __syncthreads();
    }

    for (int e = tid; e < 128 * 64; e += 768)
        g_t2[(size_t)b * CHN * 64 + e] = sA[(e >> 6) * 192 + 128 + (e & 63)];
}

// ---------------- proj via tf32 mma -------------------------------------------
#define PROJ_SMEM (128 * 72 * 4 + 2 * 8 * 264 * 4)
__global__ __launch_bounds__(256, 2) void proj_mma_kernel(float* __restrict__ out)
{
    extern __shared__ float psm[];
    float* st2 = psm;                 // [128][72]
    float* sVc = psm + 128 * 72;      // [2][8][264]

    const int tid = threadIdx.x;
    const int lane = tid & 31;
    const int wid = tid >> 5;
    const int lq = lane >> 2;
    const int lr = lane & 3;
    const int b = blockIdx.y;
    const int n0cta = blockIdx.x * 256;
    const float* Vb = g_feat + (size_t)b * CHN * NPIX;

    {
        int e4 = tid;
        for (int i = 0; i < 8; i++, e4 += 256) {
            int c = e4 >> 4, mq = e4 & 15;
            cp16(smem_u32(st2 + c * 72 + mq * 4), g_t2 + (size_t)b * CHN * 64 + c * 64 + mq * 4);
        }
    }
    auto stageV = [&](int buf, int cc) {
        int r = tid >> 6, q = tid & 63;
        cp16(smem_u32(sVc + buf * 8 * 264 + r * 264 + q * 4),
             Vb + (size_t)(cc * 8 + r) * NPIX + n0cta + q * 4);
        cp16(smem_u32(sVc + buf * 8 * 264 + (r + 4) * 264 + q * 4),
             Vb + (size_t)(cc * 8 + r + 4) * NPIX + n0cta + q * 4);
    };
    stageV(0, 0);
    CP_COMMIT();

    float acc[4][4][4];
#pragma unroll
    for (int mi = 0; mi < 4; mi++)
#pragma unroll
        for (int nj = 0; nj < 4; nj++)
#pragma unroll
            for (int e = 0; e < 4; e++) acc[mi][nj][e] = 0.f;

    for (int cc = 0; cc < 16; cc++) {
        if (cc < 15) {
            stageV((cc + 1) & 1, cc + 1);
            CP_COMMIT();
            CP_WAIT1();
        } else {
            CP_WAIT0();
        }
        __syncthreads();
        const float* sv = sVc + (cc & 1) * 8 * 264;
        uint4 af[4];
#pragma unroll
        for (int mi = 0; mi < 4; mi++) {
            int m0 = mi * 16;
            int c0 = cc * 8;
            af[mi].x = __float_as_uint(st2[(c0 + lr) * 72 + m0 + lq]);
            af[mi].y = __float_as_uint(st2[(c0 + lr) * 72 + m0 + lq + 8]);
            af[mi].z = __float_as_uint(st2[(c0 + lr + 4) * 72 + m0 + lq]);
            af[mi].w = __float_as_uint(st2[(c0 + lr + 4) * 72 + m0 + lq + 8]);
        }
#pragma unroll
        for (int nj = 0; nj < 4; nj++) {
            int n0 = wid * 32 + nj * 8;
            uint32_t b0 = __float_as_uint(sv[lr * 264 + n0 + lq]);
            uint32_t b1 = __float_as_uint(sv[(lr + 4) * 264 + n0 + lq]);
#pragma unroll
            for (int mi = 0; mi < 4; mi++) mma_tf32(acc[mi][nj], af[mi], b0, b1);
        }
        __syncthreads();
    }

#pragma unroll
    for (int mi = 0; mi < 4; mi++) {
        int m0 = mi * 16 + lq;
#pragma unroll
        for (int nj = 0; nj < 4; nj++) {
            int n = n0cta + wid * 32 + nj * 8 + lr * 2;
            *(float2*)(out + ((size_t)(b * 64 + m0)) * NPIX + n) =
                make_float2(acc[mi][nj][0], acc[mi][nj][1]);
            *(float2*)(out + ((size_t)(b * 64 + m0 + 8)) * NPIX + n) =
                make_float2(acc[mi][nj][2], acc[mi][nj][3]);
        }
    }
}

// ---------------- launch -----------------------------------------------------
extern "C" void kernel_launch(void* const* d_in, const int* in_sizes, int n_in,
                              void* d_out, int out_size)
{
    const float* x1 = (const float*)d_in[0];
    const float* x2 = (const float*)d_in[1];
    const float* w1 = (const float*)d_in[2];
    const float* b1 = (const float*)d_in[3];
    const float* w2 = (const float*)d_in[4];
    const float* b2 = (const float*)d_in[5];
    const float* wi = (const float*)d_in[6];
    const float* bi = (const float*)d_in[7];
    float* out = (float*)d_out;

    static bool attr_done = false;
    if (!attr_done) {
        cudaFuncSetAttribute(solve_kernel, cudaFuncAttributeMaxDynamicSharedMemorySize,
                             128 * 192 * sizeof(float));
        cudaFuncSetAttribute(conv_fp16_kernel<true>,
                             cudaFuncAttributeMaxDynamicSharedMemorySize, CONVH_SMEM);
        cudaFuncSetAttribute(conv_fp16_kernel<false>,
                             cudaFuncAttributeMaxDynamicSharedMemorySize, CONVH_SMEM);
        cudaFuncSetAttribute(proj_mma_kernel,
                             cudaFuncAttributeMaxDynamicSharedMemorySize, PROJ_SMEM);
        attr_done = true;
    }

    uint32_t* wh1;  cudaGetSymbolAddress((void**)&wh1, g_wh1);
    uint32_t* wh2;  cudaGetSymbolAddress((void**)&wh2, g_wh2);
    uint32_t* wih;  cudaGetSymbolAddress((void**)&wih, g_wih);

    prep_cat_kernel<<<8192, 256>>>(x1, x2);
    repack_all_kernel<<<152, 256>>>(w1, w2, wi, wh1, wh2, wih);

    dim3 cgrid(8, 16, 4);
    conv_fp16_kernel<true><<<cgrid, 256, CONVH_SMEM>>>(b1);
    gemm1x1h_kernel<<<cgrid, 256>>>(bi);
    conv_fp16_kernel<false><<<cgrid, 256, CONVH_SMEM>>>(b2);

    rowsum_scale_kernel<<<512, 256>>>();
    gemmG_mma_kernel<<<dim3(NSLICE, BATCH), 256>>>();
    reduceG_kernel<<<256, 256>>>();
    gemmT_mma_kernel<<<dim3(NSLICE, BATCH), 256>>>();
    solve_kernel<<<BATCH, 768, 128 * 192 * sizeof(float)>>>();
    proj_mma_kernel<<<dim3(64, BATCH), 256, PROJ_SMEM>>>(out);
}

// round 9
// speedup vs baseline: 1.1960x; 1.0294x over previous
#include <cuda_runtime.h>
#include <cuda_fp16.h>
#include <cstdint>
#include <cstddef>

#define NPIX 16384
#define CHN 128
#define BATCH 4
#define NSLICE 64

// ---------------- scratch (device globals; no allocation allowed) -------------
__device__ __align__(16) __half g_cath[BATCH * 8 * NPIX * 16];   // cat, fp16 interleaved
__device__ __align__(16) __half g_buf1h[BATCH * 8 * NPIX * 16];  // conv1 out, fp16 interleaved
__device__ float g_feat[BATCH * CHN * NPIX];          // 1x1 out, then feat (= unnormalized V)
__device__ float g_gpart[NSLICE * BATCH * CHN * CHN];
__device__ float g_G[BATCH * CHN * CHN];
__device__ float g_tpart[NSLICE * BATCH * CHN * 64];
__device__ float g_t2[BATCH * CHN * 64];
// fp16 conv weight fragments: [chunk8][tap9][mfrag8][lane32] uint4
__device__ uint32_t g_wh1[8 * 9 * 8 * 32 * 4];
__device__ uint32_t g_wh2[8 * 9 * 8 * 32 * 4];
__device__ uint32_t g_wih[8 * 8 * 32 * 4];            // 1x1 fp16 fragments

__device__ __forceinline__ float leakyf(float v) { return v >= 0.f ? v : 0.2f * v; }

__device__ __forceinline__ void mma_tf32(float* acc, const uint4& a, uint32_t b0, uint32_t b1) {
    asm volatile(
        "mma.sync.aligned.m16n8k8.row.col.f32.tf32.tf32.f32 "
        "{%0,%1,%2,%3}, {%4,%5,%6,%7}, {%8,%9}, {%0,%1,%2,%3};"
        : "+f"(acc[0]), "+f"(acc[1]), "+f"(acc[2]), "+f"(acc[3])
        : "r"(a.x), "r"(a.y), "r"(a.z), "r"(a.w), "r"(b0), "r"(b1));
}
__device__ __forceinline__ void mma_f16(float* acc, const uint4& a, uint32_t b0, uint32_t b1) {
    asm volatile(
        "mma.sync.aligned.m16n8k16.row.col.f32.f16.f16.f32 "
        "{%0,%1,%2,%3}, {%4,%5,%6,%7}, {%8,%9}, {%0,%1,%2,%3};"
        : "+f"(acc[0]), "+f"(acc[1]), "+f"(acc[2]), "+f"(acc[3])
        : "r"(a.x), "r"(a.y), "r"(a.z), "r"(a.w), "r"(b0), "r"(b1));
}

__device__ __forceinline__ uint32_t smem_u32(const void* p) {
    return (uint32_t)__cvta_generic_to_shared(p);
}
__device__ __forceinline__ void cp16(uint32_t s, const void* g) {
    asm volatile("cp.async.cg.shared.global [%0], [%1], 16;" :: "r"(s), "l"(g));
}
__device__ __forceinline__ void cp16z(uint32_t s, const void* g, int valid16) {
    asm volatile("cp.async.cg.shared.global [%0], [%1], 16, %2;"
                 :: "r"(s), "l"(g), "r"(valid16));
}
#define CP_COMMIT() asm volatile("cp.async.commit_group;")
#define CP_WAIT1() asm volatile("cp.async.wait_group 1;")
#define CP_WAIT0() asm volatile("cp.async.wait_group 0;")

__device__ __forceinline__ uint32_t pack_h2(float lo, float hi) {
    __half2 h = __floats2half2_rn(lo, hi);
    return *(uint32_t*)&h;
}
// permuted ic position inside 16-ic group (matches m16n8k16 B-fragment order)
__device__ __forceinline__ int icpos(int k) {
    return (k < 8) ? ((k >> 1) * 4 + (k & 1)) : (((k - 8) >> 1) * 4 + 2 + (k & 1));
}

// ---------------- prep: concat -> fp16 interleaved ----------------------------
__global__ void prep_cat_kernel(const float* __restrict__ x1, const float* __restrict__ x2)
{
    int i4 = blockIdx.x * 256 + threadIdx.x;
    if (i4 >= (BATCH * CHN * NPIX) / 4) return;
    size_t base = (size_t)i4 * 4;
    int b = (int)(base >> 21);
    int rem = (int)(base & ((1u << 21) - 1));
    int ic = rem >> 14;
    int n = rem & (NPIX - 1);
    const float* src = (ic < 64) ? x1 + ((size_t)(b * 64 + ic) << 14) + n
                                 : x2 + ((size_t)(b * 64 + ic - 64) << 14) + n;
    float4 v = *(const float4*)src;
    int chunk = ic >> 4;
    int ip = icpos(ic & 15);
    __half* hd = g_cath + (((size_t)(b * 8 + chunk) * NPIX + n) << 4) + ip;
    hd[0] = __float2half_rn(v.x);
    hd[16] = __float2half_rn(v.y);
    hd[32] = __float2half_rn(v.z);
    hd[48] = __float2half_rn(v.w);
}

// ---------------- weight repack ----------------------------------------------
__device__ __forceinline__ void repack_wh(const float* __restrict__ w, uint4* __restrict__ out,
                                          int idx)
{
    int lane = idx & 31;
    int t = idx >> 5;
    int mf = t & 7;
    int t2 = t >> 3;
    int tap = t2 % 9;
    int chunk = t2 / 9;
    int lq = lane >> 2, lr = lane & 3;
    int oc0 = mf * 16 + lq, oc1 = oc0 + 8;
    int kb = chunk * 16;
    uint4 o;
    o.x = pack_h2(w[((size_t)oc0 * CHN + kb + 2 * lr) * 9 + tap],
                  w[((size_t)oc0 * CHN + kb + 2 * lr + 1) * 9 + tap]);
    o.y = pack_h2(w[((size_t)oc1 * CHN + kb + 2 * lr) * 9 + tap],
                  w[((size_t)oc1 * CHN + kb + 2 * lr + 1) * 9 + tap]);
    o.z = pack_h2(w[((size_t)oc0 * CHN + kb + 8 + 2 * lr) * 9 + tap],
                  w[((size_t)oc0 * CHN + kb + 9 + 2 * lr) * 9 + tap]);
    o.w = pack_h2(w[((size_t)oc1 * CHN + kb + 8 + 2 * lr) * 9 + tap],
                  w[((size_t)oc1 * CHN + kb + 9 + 2 * lr) * 9 + tap]);
    out[idx] = o;
}

__global__ void repack_all_kernel(const float* __restrict__ w1, const float* __restrict__ w2,
                                  const float* __restrict__ wi,
                                  uint32_t* __restrict__ wh1, uint32_t* __restrict__ wh2,
                                  uint32_t* __restrict__ wih)
{
    int bx = blockIdx.x;
    if (bx < 72) {
        int idx = bx * 256 + threadIdx.x;
        if (idx < 18432) repack_wh(w1, (uint4*)wh1, idx);
    } else if (bx < 144) {
        int idx = (bx - 72) * 256 + threadIdx.x;
        if (idx < 18432) repack_wh(w2, (uint4*)wh2, idx);
    } else {
        int idx = (bx - 144) * 256 + threadIdx.x;
        if (idx >= 2048) return;
        int lane = idx & 31;
        int t = idx >> 5;
        int mf = t & 7;
        int chunk = t >> 3;
        int lq = lane >> 2, lr = lane & 3;
        int oc0 = mf * 16 + lq, oc1 = oc0 + 8;
        int kb = chunk * 16;
        uint4 o;
        o.x = pack_h2(wi[(size_t)oc0 * CHN + kb + 2 * lr], wi[(size_t)oc0 * CHN + kb + 2 * lr + 1]);
        o.y = pack_h2(wi[(size_t)oc1 * CHN + kb + 2 * lr], wi[(size_t)oc1 * CHN + kb + 2 * lr + 1]);
        o.z = pack_h2(wi[(size_t)oc0 * CHN + kb + 8 + 2 * lr], wi[(size_t)oc0 * CHN + kb + 9 + 2 * lr]);
        o.w = pack_h2(wi[(size_t)oc1 * CHN + kb + 8 + 2 * lr], wi[(size_t)oc1 * CHN + kb + 9 + 2 * lr]);
        ((uint4*)wih)[idx] = o;
    }
}

// ---------------- conv 3x3 via fp16 m16n8k16 ----------------------------------
// CTA 256 thr (8 warps): 128 oc x 128 px (8 rows x 16 cols); 8 chunks of 16 ic.
// Tap loop: batched B-fragment loads + double-buffered A fragments.
#define CONVH_SMEM 85248

template <bool FIRST>
__global__ __launch_bounds__(256, 2) void conv_fp16_kernel(const float* __restrict__ bias)
{
    extern __shared__ char smem[];
    uint4* sW = (uint4*)smem;                  // [2][2304]
    __half* sIn = (__half*)(smem + 73728);     // [2][10 rows][18 px][16 icperm]

    const int tid = threadIdx.x;
    const int lane = tid & 31;
    const int wid = tid >> 5;
    const int warpM = wid & 3;
    const int warpN = wid >> 2;
    const int lq = lane >> 2;
    const int lr = lane & 3;
    const int b = blockIdx.z;
    const int r0 = blockIdx.y * 8;
    const int c0 = blockIdx.x * 16;

    float acc[2][8][4];
#pragma unroll
    for (int m = 0; m < 2; m++)
#pragma unroll
        for (int j = 0; j < 8; j++)
#pragma unroll
            for (int e = 0; e < 4; e++) acc[m][j][e] = 0.f;

    const uint4* wsrc = (const uint4*)(FIRST ? g_wh1 : g_wh2);
    const __half* ibase = (FIRST ? g_cath : g_buf1h) + ((size_t)b * 8 * NPIX << 4);

    auto stw = [&](int buf, int cc) {
        const uint4* src = wsrc + (size_t)cc * 2304;
        uint4* dst = sW + buf * 2304;
#pragma unroll
        for (int i = 0; i < 9; i++) cp16(smem_u32(dst + tid + i * 256), src + tid + i * 256);
    };
    auto stin = [&](int buf, int cc) {
        const __half* src = ibase + ((size_t)cc * NPIX << 4);
        __half* dst = sIn + buf * 2880;
        for (int i = tid; i < 360; i += 256) {
            int row = i / 36;
            int p2 = i - row * 36;
            int px = p2 >> 1, hp = p2 & 1;
            int gr = r0 - 1 + row, gc = c0 - 1 + px;
            bool ok = ((unsigned)gr < 128u) && ((unsigned)gc < 128u);
            const __half* g = src + (((size_t)(ok ? gr * 128 + gc : 0)) << 4) + hp * 8;
            cp16z(smem_u32(dst + row * 288 + px * 16 + hp * 8), g, ok ? 16 : 0);
        }
    };

    stin(0, 0);
    stw(0, 0);
    CP_COMMIT();

    for (int cc = 0; cc < 8; cc++) {
        if (cc < 7) {
            stin((cc + 1) & 1, cc + 1);
            stw((cc + 1) & 1, cc + 1);
            CP_COMMIT();
            CP_WAIT1();
        } else {
            CP_WAIT0();
        }
        __syncthreads();

        const uint4* wb = sW + (cc & 1) * 2304;
        const __half* ib = sIn + (cc & 1) * 2880;

        // prime A fragments for tap 0
        uint4 a0 = wb[(0 * 8 + warpM * 2 + 0) * 32 + lane];
        uint4 a1 = wb[(0 * 8 + warpM * 2 + 1) * 32 + lane];
#pragma unroll
        for (int tap = 0; tap < 9; tap++) {
            const int dr = tap / 3, dc = tap % 3;
            // batch-load all 8 B fragments for this tap
            uint2 bv[8];
#pragma unroll
            for (int j = 0; j < 8; j++) {
                int row = warpN * 4 + (j >> 1) + dr;
                int slot = (j & 1) * 8 + lq + dc;
                bv[j] = *(const uint2*)(ib + row * 288 + slot * 16 + lr * 4);
            }
            // prefetch next tap's A fragments
            uint4 na0, na1;
            if (tap < 8) {
                na0 = wb[((tap + 1) * 8 + warpM * 2 + 0) * 32 + lane];
                na1 = wb[((tap + 1) * 8 + warpM * 2 + 1) * 32 + lane];
            }
#pragma unroll
            for (int j = 0; j < 8; j++) {
                mma_f16(acc[0][j], a0, bv[j].x, bv[j].y);
                mma_f16(acc[1][j], a1, bv[j].x, bv[j].y);
            }
            if (tap < 8) { a0 = na0; a1 = na1; }
        }
        __syncthreads();
    }

    // ---- epilogue ----
#pragma unroll
    for (int m = 0; m < 2; m++) {
        int oc = warpM * 32 + m * 16 + lq;
        float bv0 = bias[oc], bv1 = bias[oc + 8];
        if (FIRST) {
            const int chunk = warpM * 2 + m;
            const int ip0 = icpos(lq), ip1 = icpos(lq + 8);
            __half* hb = g_buf1h + (((size_t)(b * 8 + chunk) * NPIX) << 4);
#pragma unroll
            for (int j = 0; j < 8; j++) {
                int pix = (r0 + warpN * 4 + (j >> 1)) * 128 + c0 + (j & 1) * 8 + lr * 2;
                __half* p = hb + ((size_t)pix << 4);
                p[ip0] = __float2half_rn(leakyf(acc[m][j][0] + bv0));
                p[16 + ip0] = __float2half_rn(leakyf(acc[m][j][1] + bv0));
                p[ip1] = __float2half_rn(leakyf(acc[m][j][2] + bv1));
                p[16 + ip1] = __float2half_rn(leakyf(acc[m][j][3] + bv1));
            }
        } else {
#pragma unroll
            for (int j = 0; j < 8; j++) {
                int irow = r0 + warpN * 4 + (j >> 1);
                int icol = c0 + (j & 1) * 8 + lr * 2;
                size_t base0 = ((size_t)(b * CHN + oc) * 128 + irow) * 128 + icol;
                size_t base1 = base0 + (size_t)8 * NPIX;
                float2 p0 = *(const float2*)(g_feat + base0);
                float2 p1 = *(const float2*)(g_feat + base1);
                p0.x += leakyf(acc[m][j][0] + bv0);
                p0.y += leakyf(acc[m][j][1] + bv0);
                p1.x += leakyf(acc[m][j][2] + bv1);
                p1.y += leakyf(acc[m][j][3] + bv1);
                *(float2*)(g_feat + base0) = p0;
                *(float2*)(g_feat + base1) = p1;
            }
        }
    }
}

// ---------------- 1x1 conv via fp16 m16n8k16 (reuses g_cath) ------------------
__global__ __launch_bounds__(256) void gemm1x1h_kernel(const float* __restrict__ bi)
{
    __shared__ uint4 sW1[2][256];
    __shared__ __half sB[2][2048];   // [row8][px16][16icp]

    const int tid = threadIdx.x;
    const int lane = tid & 31;
    const int wid = tid >> 5;
    const int warpM = wid & 3;
    const int warpN = wid >> 2;
    const int lq = lane >> 2;
    const int lr = lane & 3;
    const int b = blockIdx.z;
    const int r0 = blockIdx.y * 8;
    const int c0 = blockIdx.x * 16;

    float acc[2][8][4];
#pragma unroll
    for (int m = 0; m < 2; m++)
#pragma unroll
        for (int j = 0; j < 8; j++)
#pragma unroll
            for (int e = 0; e < 4; e++) acc[m][j][e] = 0.f;

    const __half* ibase = g_cath + ((size_t)b * 8 * NPIX << 4);

    auto stage = [&](int buf, int cc) {
        int hp = tid & 1;
        int pl = tid >> 1;
        int row = pl >> 4, px = pl & 15;
        int pix = (r0 + row) * 128 + c0 + px;
        cp16(smem_u32(&sB[buf][(row * 16 + px) * 16 + hp * 8]),
             ibase + ((size_t)cc * NPIX << 4) + ((size_t)pix << 4) + hp * 8);
        cp16(smem_u32(&sW1[buf][tid]), ((const uint4*)g_wih) + cc * 256 + tid);
    };

    stage(0, 0);
    CP_COMMIT();

    for (int cc = 0; cc < 8; cc++) {
        if (cc < 7) {
            stage((cc + 1) & 1, cc + 1);
            CP_COMMIT();
            CP_WAIT1();
        } else {
            CP_WAIT0();
        }
        __syncthreads();

        uint4 a0 = sW1[cc & 1][(warpM * 2 + 0) * 32 + lane];
        uint4 a1 = sW1[cc & 1][(warpM * 2 + 1) * 32 + lane];
        const __half* ib = sB[cc & 1];
        uint2 bv[8];
#pragma unroll
        for (int j = 0; j < 8; j++) {
            int row = warpN * 4 + (j >> 1);
            int slot = (j & 1) * 8 + lq;
            bv[j] = *(const uint2*)(ib + (row * 16 + slot) * 16 + lr * 4);
        }
#pragma unroll
        for (int j = 0; j < 8; j++) {
            mma_f16(acc[0][j], a0, bv[j].x, bv[j].y);
            mma_f16(acc[1][j], a1, bv[j].x, bv[j].y);
        }
        __syncthreads();
    }

#pragma unroll
    for (int m = 0; m < 2; m++) {
        int oc = warpM * 32 + m * 16 + lq;
        float b0 = bi[oc], b1 = bi[oc + 8];
#pragma unroll
        for (int j = 0; j < 8; j++) {
            int irow = r0 + warpN * 4 + (j >> 1);
            int icol = c0 + (j & 1) * 8 + lr * 2;
            size_t base0 = ((size_t)(b * CHN + oc) * 128 + irow) * 128 + icol;
            size_t base1 = base0 + (size_t)8 * NPIX;
            *(float2*)(g_feat + base0) = make_float2(acc[m][j][0] + b0, acc[m][j][1] + b0);
            *(float2*)(g_feat + base1) = make_float2(acc[m][j][2] + b1, acc[m][j][3] + b1);
        }
    }
}

// ---------------- G = V V^T via tf32 mma, split-K -----------------------------
// (V = unnormalized feat; projection is invariant to row scaling, so the L1
//  normalization of the reference cancels mathematically and is skipped.)
__global__ __launch_bounds__(256, 2) void gemmG_mma_kernel()
{
    __shared__ float sV[2][128 * 20];
    const int tid = threadIdx.x;
    const int lane = tid & 31;
    const int wid = tid >> 5;
    const int warpM = wid & 3;
    const int warpN = wid >> 2;
    const int lq = lane >> 2;
    const int lr = lane & 3;
    const int slice = blockIdx.x, b = blockIdx.y;
    const float* base = g_feat + (size_t)b * CHN * NPIX;
    const int k0g = slice * 256;

    float acc[2][8][4];
#pragma unroll
    for (int mi = 0; mi < 2; mi++)
#pragma unroll
        for (int nj = 0; nj < 8; nj++)
#pragma unroll
            for (int e = 0; e < 4; e++) acc[mi][nj][e] = 0.f;

    {
        int c = tid >> 1, q = tid & 1;
        cp16(smem_u32(&sV[0][c * 20 + q * 8]), base + (size_t)c * NPIX + k0g + q * 8);
        cp16(smem_u32(&sV[0][c * 20 + q * 8 + 4]), base + (size_t)c * NPIX + k0g + q * 8 + 4);
    }
    CP_COMMIT();

    for (int kc = 0; kc < 16; kc++) {
        if (kc < 15) {
            int c = tid >> 1, q = tid & 1;
            int kk = k0g + (kc + 1) * 16;
            cp16(smem_u32(&sV[(kc + 1) & 1][c * 20 + q * 8]), base + (size_t)c * NPIX + kk + q * 8);
            cp16(smem_u32(&sV[(kc + 1) & 1][c * 20 + q * 8 + 4]),
                 base + (size_t)c * NPIX + kk + q * 8 + 4);
            CP_COMMIT();
            CP_WAIT1();
        } else {
            CP_WAIT0();
        }
        __syncthreads();
        const float* sv = sV[kc & 1];
#pragma unroll
        for (int ks = 0; ks < 2; ks++) {
            int k = ks * 8;
            uint4 af[2];
#pragma unroll
            for (int mi = 0; mi < 2; mi++) {
                int m0 = warpM * 32 + mi * 16;
                af[mi].x = __float_as_uint(sv[(m0 + lq) * 20 + k + lr]);
                af[mi].y = __float_as_uint(sv[(m0 + lq + 8) * 20 + k + lr]);
                af[mi].z = __float_as_uint(sv[(m0 + lq) * 20 + k + lr + 4]);
                af[mi].w = __float_as_uint(sv[(m0 + lq + 8) * 20 + k + lr + 4]);
            }
#pragma unroll
            for (int nj = 0; nj < 8; nj++) {
                int n0 = warpN * 64 + nj * 8;
                uint32_t b0 = __float_as_uint(sv[(n0 + lq) * 20 + k + lr]);
                uint32_t b1 = __float_as_uint(sv[(n0 + lq) * 20 + k + lr + 4]);
                mma_tf32(acc[0][nj], af[0], b0, b1);
                mma_tf32(acc[1][nj], af[1], b0, b1);
            }
        }
        __syncthreads();
    }

    float* outp = g_gpart + ((size_t)slice * BATCH + b) * CHN * CHN;
#pragma unroll
    for (int mi = 0; mi < 2; mi++) {
        int m0 = warpM * 32 + mi * 16 + lq;
#pragma unroll
        for (int nj = 0; nj < 8; nj++) {
            int n = warpN * 64 + nj * 8 + lr * 2;
            *(float2*)(outp + m0 * 128 + n) = make_float2(acc[mi][nj][0], acc[mi][nj][1]);
            *(float2*)(outp + (m0 + 8) * 128 + n) = make_float2(acc[mi][nj][2], acc[mi][nj][3]);
        }
    }
}

__global__ void reduceG_kernel()
{
    int o = blockIdx.x * 256 + threadIdx.x;
    float s = 0.f;
    for (int sl = 0; sl < NSLICE; sl++)
        s += g_gpart[(size_t)sl * (BATCH * CHN * CHN) + o];
    g_G[o] = s;
}

// ---------------- t = V @ x1^T via tf32 mma, split-K --------------------------
__global__ __launch_bounds__(256, 2) void gemmT_mma_kernel(const float* __restrict__ x1)
{
    __shared__ float sV[2][128 * 20];
    __shared__ float sX[2][64 * 20];
    const int tid = threadIdx.x;
    const int lane = tid & 31;
    const int wid = tid >> 5;
    const int warpM = wid & 3;
    const int warpN = wid >> 2;
    const int lq = lane >> 2;
    const int lr = lane & 3;
    const int slice = blockIdx.x, b = blockIdx.y;
    const float* vbase = g_feat + (size_t)b * CHN * NPIX;
    const float* xbase = x1 + (size_t)b * 64 * NPIX;
    const int k0g = slice * 256;

    float acc[2][4][4];
#pragma unroll
    for (int mi = 0; mi < 2; mi++)
#pragma unroll
        for (int nj = 0; nj < 4; nj++)
#pragma unroll
            for (int e = 0; e < 4; e++) acc[mi][nj][e] = 0.f;

    auto stage = [&](int buf, int kc) {
        int kk = k0g + kc * 16;
        int c = tid >> 1, q = tid & 1;
        cp16(smem_u32(&sV[buf][c * 20 + q * 8]), vbase + (size_t)c * NPIX + kk + q * 8);
        cp16(smem_u32(&sV[buf][c * 20 + q * 8 + 4]), vbase + (size_t)c * NPIX + kk + q * 8 + 4);
        int m = tid >> 2, q2 = tid & 3;
        cp16(smem_u32(&sX[buf][m * 20 + q2 * 4]), xbase + (size_t)m * NPIX + kk + q2 * 4);
    };

    stage(0, 0);
    CP_COMMIT();

    for (int kc = 0; kc < 16; kc++) {
        if (kc < 15) {
            stage((kc + 1) & 1, kc + 1);
            CP_COMMIT();
            CP_WAIT1();
        } else {
            CP_WAIT0();
        }
        __syncthreads();
        const float* sv = sV[kc & 1];
        const float* sx = sX[kc & 1];
#pragma unroll
        for (int ks = 0; ks < 2; ks++) {
            int k = ks * 8;
            uint4 af[2];
#pragma unroll
            for (int mi = 0; mi < 2; mi++) {
                int m0 = warpM * 32 + mi * 16;
                af[mi].x = __float_as_uint(sv[(m0 + lq) * 20 + k + lr]);
                af[mi].y = __float_as_uint(sv[(m0 + lq + 8) * 20 + k + lr]);
                af[mi].z = __float_as_uint(sv[(m0 + lq) * 20 + k + lr + 4]);
                af[mi].w = __float_as_uint(sv[(m0 + lq + 8) * 20 + k + lr + 4]);
            }
#pragma unroll
            for (int nj = 0; nj < 4; nj++) {
                int n0 = warpN * 32 + nj * 8;
                uint32_t b0 = __float_as_uint(sx[(n0 + lq) * 20 + k + lr]);
                uint32_t b1 = __float_as_uint(sx[(n0 + lq) * 20 + k + lr + 4]);
                mma_tf32(acc[0][nj], af[0], b0, b1);
                mma_tf32(acc[1][nj], af[1], b0, b1);
            }
        }
        __syncthreads();
    }

    float* outp = g_tpart + ((size_t)slice * BATCH + b) * CHN * 64;
#pragma unroll
    for (int mi = 0; mi < 2; mi++) {
        int m0 = warpM * 32 + mi * 16 + lq;
#pragma unroll
        for (int nj = 0; nj < 4; nj++) {
            int n = warpN * 32 + nj * 8 + lr * 2;
            *(float2*)(outp + m0 * 64 + n) = make_float2(acc[mi][nj][0], acc[mi][nj][1]);
            *(float2*)(outp + (m0 + 8) * 64 + n) = make_float2(acc[mi][nj][2], acc[mi][nj][3]);
        }
    }
}

// ---------------- solve: [G | t] -> G^{-1} t, in shared memory ---------------
__global__ __launch_bounds__(768) void solve_kernel()
{
    extern __shared__ float sA[];  // [128][192]
    __shared__ float fcol[128];
    __shared__ float prow[192];
    const int b = blockIdx.x, tid = threadIdx.x;

    for (int i = tid; i < 128 * 128; i += 768) {
        int r = i >> 7, c = i & 127;
        sA[r * 192 + c] = g_G[(size_t)b * CHN * CHN + i];
    }
    for (int e = tid; e < 128 * 64; e += 768) {
        float s = 0.f;
        for (int sl = 0; sl < NSLICE; sl++)
            s += g_tpart[((size_t)sl * BATCH + b) * CHN * 64 + e];
        sA[(e >> 6) * 192 + 128 + (e & 63)] = s;
    }
    __syncthreads();

    const int j = tid % 192, g = tid / 192;
    for (int p = 0; p < 128; p++) {
        if (g == 0) {
            float piv = sA[p * 192 + p];
            prow[j] = sA[p * 192 + j] * (1.0f / piv);
        } else if (g == 1 && j < 128) {
            fcol[j] = (j == p) ? 0.f : sA[j * 192 + p];
        }
        __syncthreads();
        float pr = prow[j];
        const int i0 = g * 32;
#pragma unroll 4
        for (int i = i0; i < i0 + 32; i++) {
            float v = sA[i * 192 + j] - fcol[i] * pr;
            if (i == p) v = pr;
            sA[i * 192 + j] = v;
        }
        __syncthreads();
    }

    for (int e = tid; e < 128 * 64; e += 768)
        g_t2[(size_t)b * CHN * 64 + e] = sA[(e >> 6) * 192 + 128 + (e & 63)];
}

// ---------------- proj via tf32 mma -------------------------------------------
#define PROJ_SMEM (128 * 72 * 4 + 2 * 8 * 264 * 4)
__global__ __launch_bounds__(256, 2) void proj_mma_kernel(float* __restrict__ out)
{
    extern __shared__ float psm[];
    float* st2 = psm;                 // [128][72]
    float* sVc = psm + 128 * 72;      // [2][8][264]

    const int tid = threadIdx.x;
    const int lane = tid & 31;
    const int wid = tid >> 5;
    const int lq = lane >> 2;
    const int lr = lane & 3;
    const int b = blockIdx.y;
    const int n0cta = blockIdx.x * 256;
    const float* Vb = g_feat + (size_t)b * CHN * NPIX;

    {
        int e4 = tid;
        for (int i = 0; i < 8; i++, e4 += 256) {
            int c = e4 >> 4, mq = e4 & 15;
            cp16(smem_u32(st2 + c * 72 + mq * 4), g_t2 + (size_t)b * CHN * 64 + c * 64 + mq * 4);
        }
    }
    auto stageV = [&](int buf, int cc) {
        int r = tid >> 6, q = tid & 63;
        cp16(smem_u32(sVc + buf * 8 * 264 + r * 264 + q * 4),
             Vb + (size_t)(cc * 8 + r) * NPIX + n0cta + q * 4);
        cp16(smem_u32(sVc + buf * 8 * 264 + (r + 4) * 264 + q * 4),
             Vb + (size_t)(cc * 8 + r + 4) * NPIX + n0cta + q * 4);
    };
    stageV(0, 0);
    CP_COMMIT();

    float acc[4][4][4];
#pragma unroll
    for (int mi = 0; mi < 4; mi++)
#pragma unroll
        for (int nj = 0; nj < 4; nj++)
#pragma unroll
            for (int e = 0; e < 4; e++) acc[mi][nj][e] = 0.f;

    for (int cc = 0; cc < 16; cc++) {
        if (cc < 15) {
            stageV((cc + 1) & 1, cc + 1);
            CP_COMMIT();
            CP_WAIT1();
        } else {
            CP_WAIT0();
        }
        __syncthreads();
        const float* sv = sVc + (cc & 1) * 8 * 264;
        uint4 af[4];
#pragma unroll
        for (int mi = 0; mi < 4; mi++) {
            int m0 = mi * 16;
            int c0 = cc * 8;
            af[mi].x = __float_as_uint(st2[(c0 + lr) * 72 + m0 + lq]);
            af[mi].y = __float_as_uint(st2[(c0 + lr) * 72 + m0 + lq + 8]);
            af[mi].z = __float_as_uint(st2[(c0 + lr + 4) * 72 + m0 + lq]);
            af[mi].w = __float_as_uint(st2[(c0 + lr + 4) * 72 + m0 + lq + 8]);
        }
#pragma unroll
        for (int nj = 0; nj < 4; nj++) {
            int n0 = wid * 32 + nj * 8;
            uint32_t b0 = __float_as_uint(sv[lr * 264 + n0 + lq]);
            uint32_t b1 = __float_as_uint(sv[(lr + 4) * 264 + n0 + lq]);
#pragma unroll
            for (int mi = 0; mi < 4; mi++) mma_tf32(acc[mi][nj], af[mi], b0, b1);
        }
        __syncthreads();
    }

#pragma unroll
    for (int mi = 0; mi < 4; mi++) {
        int m0 = mi * 16 + lq;
#pragma unroll
        for (int nj = 0; nj < 4; nj++) {
            int n = n0cta + wid * 32 + nj * 8 + lr * 2;
            *(float2*)(out + ((size_t)(b * 64 + m0)) * NPIX + n) =
                make_float2(acc[mi][nj][0], acc[mi][nj][1]);
            *(float2*)(out + ((size_t)(b * 64 + m0 + 8)) * NPIX + n) =
                make_float2(acc[mi][nj][2], acc[mi][nj][3]);
        }
    }
}

// ---------------- launch -----------------------------------------------------
extern "C" void kernel_launch(void* const* d_in, const int* in_sizes, int n_in,
                              void* d_out, int out_size)
{
    const float* x1 = (const float*)d_in[0];
    const float* x2 = (const float*)d_in[1];
    const float* w1 = (const float*)d_in[2];
    const float* b1 = (const float*)d_in[3];
    const float* w2 = (const float*)d_in[4];
    const float* b2 = (const float*)d_in[5];
    const float* wi = (const float*)d_in[6];
    const float* bi = (const float*)d_in[7];
    float* out = (float*)d_out;

    static bool attr_done = false;
    if (!attr_done) {
        cudaFuncSetAttribute(solve_kernel, cudaFuncAttributeMaxDynamicSharedMemorySize,
                             128 * 192 * sizeof(float));
        cudaFuncSetAttribute(conv_fp16_kernel<true>,
                             cudaFuncAttributeMaxDynamicSharedMemorySize, CONVH_SMEM);
        cudaFuncSetAttribute(conv_fp16_kernel<false>,
                             cudaFuncAttributeMaxDynamicSharedMemorySize, CONVH_SMEM);
        cudaFuncSetAttribute(proj_mma_kernel,
                             cudaFuncAttributeMaxDynamicSharedMemorySize, PROJ_SMEM);
        attr_done = true;
    }

    uint32_t* wh1;  cudaGetSymbolAddress((void**)&wh1, g_wh1);
    uint32_t* wh2;  cudaGetSymbolAddress((void**)&wh2, g_wh2);
    uint32_t* wih;  cudaGetSymbolAddress((void**)&wih, g_wih);

    prep_cat_kernel<<<8192, 256>>>(x1, x2);
    repack_all_kernel<<<152, 256>>>(w1, w2, wi, wh1, wh2, wih);

    dim3 cgrid(8, 16, 4);
    conv_fp16_kernel<true><<<cgrid, 256, CONVH_SMEM>>>(b1);
    gemm1x1h_kernel<<<cgrid, 256>>>(bi);
    conv_fp16_kernel<false><<<cgrid, 256, CONVH_SMEM>>>(b2);

    gemmG_mma_kernel<<<dim3(NSLICE, BATCH), 256>>>();
    reduceG_kernel<<<256, 256>>>();
    gemmT_mma_kernel<<<dim3(NSLICE, BATCH), 256>>>(x1);
    solve_kernel<<<BATCH, 768, 128 * 192 * sizeof(float)>>>();
    proj_mma_kernel<<<dim3(64, BATCH), 256, PROJ_SMEM>>>(out);
}